// round 10
// baseline (speedup 1.0000x reference)
#include <cuda_runtime.h>
#include <math.h>
#include <stdint.h>

#define NQ 16384
#define CC 256
#define EE 256
#define LL 5
#define NHH 4
#define PP 4
#define HDD 64
#define FFH 512
#define NLAY 6
#define NOA 240

// ---------------- scratch (device globals; no allocation) ----------------
__device__ float g_f[LL * CC * NQ];     // normed features, [l][c][n] K-major, tf32-rounded
__device__ float g_q[NQ * EE];          // query fp32 [n][e]
__device__ float g_qr[NQ * EE];         // permuted tf32 q      (ffn1 A)
__device__ float g_qp[NQ * EE];         // permuted tf32 q+pos  (oa A)
__device__ float g_pos[NQ * EE];
__device__ float g_offaw[NQ * NOA];     // fp32 [n][240]
__device__ float g_val[LL * NQ * EE];   // [l][n][e]
__device__ float g_acc[NQ * EE];        // permuted tf32 (out-proj A)
__device__ float g_h[NQ * FFH];         // permuted tf32 (ffn2 A)
// tf32-rounded weights, [K][N]
__device__ float g_w_in[1280 * 256];
__device__ float g_w_oa[NLAY * 256 * NOA + 64];   // +64 pad for N-tile overrun reads
__device__ float g_w_val[NLAY * 256 * 256];
__device__ float g_w_out[NLAY * 256 * 256];
__device__ float g_w_f1[NLAY * 256 * 512];
__device__ float g_w_f2[NLAY * 512 * 256];
__device__ float g_b_oa[NLAY * NOA];

// ---------------- helpers ----------------
__device__ __forceinline__ float f2tf(float x) {
    unsigned u;
    asm("cvt.rna.tf32.f32 %0, %1;" : "=r"(u) : "f"(x));
    return __uint_as_float(u);
}
__device__ __forceinline__ uint32_t smem_u32(const void* p) {
    uint32_t a;
    asm("{ .reg .u64 t; cvta.to.shared.u64 t, %1; cvt.u32.u64 %0, t; }" : "=r"(a) : "l"(p));
    return a;
}
// column permutation within aligned 8-groups: k -> (k&3)*2 + (k>>2)
__device__ __forceinline__ int permc(int c) {
    return (c & ~7) | (((c & 3) << 1) | ((c >> 2) & 1));
}
__device__ __forceinline__ void mma_tf32(float* cc, const unsigned* a, const unsigned* b) {
    asm volatile(
        "mma.sync.aligned.m16n8k8.row.col.f32.tf32.tf32.f32 "
        "{%0,%1,%2,%3}, {%4,%5,%6,%7}, {%8,%9}, {%0,%1,%2,%3};\n"
        : "+f"(cc[0]), "+f"(cc[1]), "+f"(cc[2]), "+f"(cc[3])
        : "r"(a[0]), "r"(a[1]), "r"(a[2]), "r"(a[3]), "r"(b[0]), "r"(b[1]));
}
#define CPA16(sa, ga) asm volatile("cp.async.cg.shared.global [%0], [%1], 16;" :: "r"(sa), "l"(ga) : "memory")
#define CPA_COMMIT()  asm volatile("cp.async.commit_group;" ::: "memory")
#define CPA_WAIT(n)   asm volatile("cp.async.wait_group %0;" :: "n"(n) : "memory")

// ---------------- prologue kernels ----------------
__global__ void rcopy5_kernel(const float* __restrict__ s0, float* __restrict__ d0, int n0,
                              const float* __restrict__ s1, float* __restrict__ d1, int n1,
                              const float* __restrict__ s2, float* __restrict__ d2, int n2,
                              const float* __restrict__ s3, float* __restrict__ d3, int n3,
                              const float* __restrict__ s4, float* __restrict__ d4, int n4) {
    int i = blockIdx.x * 256 + threadIdx.x;
    if (i < n0) d0[i] = f2tf(s0[i]);
    if (i < n1) d1[i] = f2tf(s1[i]);
    if (i < n2) d2[i] = f2tf(s2[i]);
    if (i < n3) d3[i] = f2tf(s3[i]);
    if (i < n4) d4[i] = f2tf(s4[i]);
}

__global__ void pack_oa_kernel(const float* __restrict__ off_w, const float* __restrict__ off_b,
                               const float* __restrict__ aw_w, const float* __restrict__ aw_b) {
    int idx = blockIdx.x * 256 + threadIdx.x;
    if (idx >= NLAY * EE * NOA) return;
    int c = idx % NOA;
    int e = (idx / NOA) % EE;
    int i = idx / (NOA * EE);
    float v = (c < 160) ? off_w[((size_t)i * EE + e) * 160 + c]
                        : aw_w[((size_t)i * EE + e) * 80 + (c - 160)];
    g_w_oa[idx] = f2tf(v);
    if (e == 0)
        g_b_oa[i * NOA + c] = (c < 160) ? off_b[i * 160 + c] : aw_b[i * 80 + (c - 160)];
}

__global__ void norm0_kernel(const float* __restrict__ feat,
                             const float* __restrict__ g,
                             const float* __restrict__ b) {
    int n = blockIdx.x * blockDim.x + threadIdx.x;
    int l = blockIdx.y;
    const float* src = feat + (size_t)l * CC * NQ + n;
    float sum = 0.f, sq = 0.f;
#pragma unroll 8
    for (int c = 0; c < CC; c++) {
        float v = src[(size_t)c * NQ];
        sum += v; sq += v * v;
    }
    float mean = sum * (1.f / CC);
    float var = sq * (1.f / CC) - mean * mean;
    float rstd = rsqrtf(var + 1e-5f);
    float* dst = g_f + (size_t)l * CC * NQ + n;
#pragma unroll 8
    for (int c = 0; c < CC; c++)
        dst[(size_t)c * NQ] = f2tf((src[(size_t)c * NQ] - mean) * rstd * g[l * CC + c] + b[l * CC + c]);
}

__global__ void pos_kernel(const float* __restrict__ prow, const float* __restrict__ pcol) {
    int i = blockIdx.x * 256 + threadIdx.x;
    int n = i >> 8, e = i & 255;
    int hh = n >> 7, ww = n & 127;
    g_pos[i] = (e < 128) ? pcol[ww * 128 + e] : prow[hh * 128 + (e - 128)];
}

// ---------------- tf32 tensor-core GEMM core, cp.async 4-stage pipeline ----------------
#define APAD 24
#define BPAD 136
#define STAGES 4
#define ROW_SMEM (STAGES * (128 * APAD + 16 * BPAD) * 4)
#define AKM_SMEM (STAGES * (16 * BPAD + 16 * BPAD) * 4)

template <bool AKM, bool RELU, bool ROUNDC, bool AUXQP>
__device__ __forceinline__ void gemm_core(
    const float* __restrict__ A, const float* __restrict__ B,
    const float* __restrict__ bias, const float* __restrict__ resid,
    float* __restrict__ C, float* __restrict__ Caux, const float* __restrict__ Pos,
    int N, int K, int lda, size_t aBlockStride) {
    extern __shared__ __align__(16) char sraw[];
    constexpr int ASF = AKM ? (16 * BPAD) : (128 * APAD);
    constexpr int BSF = 16 * BPAD;
    float* AsBase = (float*)sraw;
    float* BsBase = (float*)sraw + STAGES * ASF;

    const int tid = threadIdx.x;
    const int warp = tid >> 5, lane = tid & 31;
    const int m0 = blockIdx.y * 128, n0 = blockIdx.x * 128;
    const int wm = (warp & 3) * 32, wn = (warp >> 2) * 64;
    const int r = lane >> 2, cq = lane & 3;

    const uint32_t uA = smem_u32(AsBase);
    const uint32_t uB = smem_u32(BsBase);
    const int KT = K >> 4;

    float acc[2][8][4];
#pragma unroll
    for (int mt = 0; mt < 2; mt++)
#pragma unroll
        for (int nt = 0; nt < 8; nt++)
#pragma unroll
            for (int k = 0; k < 4; k++) acc[mt][nt][k] = 0.f;

    auto ld_stage = [&](int kt) {
        int st = kt & (STAGES - 1);
        int kk = kt << 4;
        if (AKM) {
            int blk = kk >> 8;
            int kin = kk & 255;
            const float* base = A + (size_t)blk * aBlockStride;
#pragma unroll
            for (int t = 0; t < 2; t++) {
                int ch = tid + t * 256;
                int j = ch >> 5, co = (ch & 31) << 2;
                CPA16(uA + (uint32_t)(st * ASF + j * BPAD + co) * 4,
                      base + (size_t)(kin + j) * lda + m0 + co);
            }
        } else {
#pragma unroll
            for (int t = 0; t < 2; t++) {
                int ch = tid + t * 256;
                int i = ch >> 2, kc = (ch & 3) << 2;
                CPA16(uA + (uint32_t)(st * ASF + i * APAD + kc) * 4,
                      A + (size_t)(m0 + i) * lda + kk + kc);
            }
        }
#pragma unroll
        for (int t = 0; t < 2; t++) {
            int ch = tid + t * 256;
            int j = ch >> 5, co = (ch & 31) << 2;
            CPA16(uB + (uint32_t)(st * BSF + j * BPAD + co) * 4,
                  B + (size_t)(kk + j) * N + n0 + co);
        }
    };

#pragma unroll
    for (int s = 0; s < STAGES - 1; s++) { ld_stage(s); CPA_COMMIT(); }

    for (int kt = 0; kt < KT; kt++) {
        CPA_WAIT(STAGES - 2);
        __syncthreads();
        if (kt + STAGES - 1 < KT) ld_stage(kt + STAGES - 1);
        CPA_COMMIT();

        const float* a_s = AsBase + (kt & (STAGES - 1)) * ASF;
        const float* b_s = BsBase + (kt & (STAGES - 1)) * BSF;
#pragma unroll
        for (int k8 = 0; k8 < 16; k8 += 8) {
            unsigned af[2][4], bf[8][2];
            if (AKM) {
#pragma unroll
                for (int mt = 0; mt < 2; mt++) {
                    int mb = wm + mt * 16 + r;
                    af[mt][0] = ((const unsigned*)a_s)[(k8 + cq) * BPAD + mb];
                    af[mt][1] = ((const unsigned*)a_s)[(k8 + cq) * BPAD + mb + 8];
                    af[mt][2] = ((const unsigned*)a_s)[(k8 + cq + 4) * BPAD + mb];
                    af[mt][3] = ((const unsigned*)a_s)[(k8 + cq + 4) * BPAD + mb + 8];
                }
            } else {
#pragma unroll
                for (int mt = 0; mt < 2; mt++) {
                    int mb = wm + mt * 16 + r;
                    float2 p0 = *(const float2*)(a_s + mb * APAD + k8 + 2 * cq);
                    float2 p1 = *(const float2*)(a_s + (mb + 8) * APAD + k8 + 2 * cq);
                    af[mt][0] = __float_as_uint(p0.x);
                    af[mt][1] = __float_as_uint(p1.x);
                    af[mt][2] = __float_as_uint(p0.y);
                    af[mt][3] = __float_as_uint(p1.y);
                }
            }
#pragma unroll
            for (int nt = 0; nt < 8; nt++) {
                int nb = wn + nt * 8 + r;
                bf[nt][0] = ((const unsigned*)b_s)[(k8 + cq) * BPAD + nb];
                bf[nt][1] = ((const unsigned*)b_s)[(k8 + cq + 4) * BPAD + nb];
            }
#pragma unroll
            for (int mt = 0; mt < 2; mt++)
#pragma unroll
                for (int nt = 0; nt < 8; nt++)
                    mma_tf32(acc[mt][nt], af[mt], bf[nt]);
        }
    }

    // ---- epilogue ----
#pragma unroll
    for (int mt = 0; mt < 2; mt++) {
#pragma unroll
        for (int nt = 0; nt < 8; nt++) {
            int row = m0 + wm + mt * 16 + r;
            int col = n0 + wn + nt * 8 + 2 * cq;
            if (col < N) {
                float b0 = bias[col], b1 = bias[col + 1];
#pragma unroll
                for (int hh = 0; hh < 2; hh++) {
                    int rr = row + hh * 8;
                    float v0 = acc[mt][nt][hh * 2 + 0] + b0;
                    float v1 = acc[mt][nt][hh * 2 + 1] + b1;
                    if (resid) {
                        float2 rv = *(const float2*)(resid + (size_t)rr * N + col);
                        v0 += rv.x; v1 += rv.y;
                    }
                    if (RELU) { v0 = fmaxf(v0, 0.f); v1 = fmaxf(v1, 0.f); }
                    if (ROUNDC) {
                        C[(size_t)rr * N + permc(col)]     = f2tf(v0);
                        C[(size_t)rr * N + permc(col + 1)] = f2tf(v1);
                    } else {
                        *(float2*)(C + (size_t)rr * N + col) = make_float2(v0, v1);
                        if (AUXQP) {
                            float p0 = Pos[(size_t)rr * 256 + col];
                            float p1 = Pos[(size_t)rr * 256 + col + 1];
                            Caux[(size_t)rr * 256 + permc(col)]     = f2tf(v0 + p0);
                            Caux[(size_t)rr * 256 + permc(col + 1)] = f2tf(v1 + p1);
                        }
                    }
                }
            }
        }
    }
}

// standalone GEMM kernel
template <bool AKM, bool RELU, bool ROUNDC, bool AUXQP>
__global__ void __launch_bounds__(256, 2) gemm_ca(
    const float* __restrict__ A, const float* __restrict__ B,
    const float* __restrict__ bias, const float* __restrict__ resid,
    float* __restrict__ C, float* __restrict__ Caux, const float* __restrict__ Pos,
    int N, int K, int lda, size_t aBlockStride) {
    gemm_core<AKM, RELU, ROUNDC, AUXQP>(A, B, bias, resid, C, Caux, Pos,
                                        N, K, lda, aBlockStride);
}

// merged oa + val launch: z=0 -> oa (row path), z=1..5 -> val level z-1 (AKM path)
__global__ void __launch_bounds__(256, 2) gemm_oaval(
    const float* __restrict__ Aoa, const float* __restrict__ Boa,
    const float* __restrict__ boa, float* __restrict__ Coa,
    const float* __restrict__ Af, const float* __restrict__ Bval,
    const float* __restrict__ bval, float* __restrict__ Cval) {
    if (blockIdx.z == 0) {
        gemm_core<false, false, false, false>(Aoa, Boa, boa, nullptr, Coa, nullptr, nullptr,
                                              NOA, 256, 256, 0);
    } else {
        int zz = blockIdx.z - 1;
        gemm_core<true, false, false, false>(Af + (size_t)zz * CC * NQ, Bval, bval, nullptr,
                                             Cval + (size_t)zz * NQ * EE, nullptr, nullptr,
                                             256, 256, NQ, (size_t)CC * NQ);
    }
}

// ---------------- fused softmax + bilinear deformable sampling ----------------
__global__ void __launch_bounds__(512) sample_kernel(
        const float* __restrict__ offaw,
        const float* __restrict__ val,
        float* __restrict__ acc) {
    int w = threadIdx.y;
    int n = blockIdx.x * 4 + (w >> 2);
    int h = w & 3;
    int lane = threadIdx.x;

    float logit = (lane < 20) ? offaw[(size_t)n * NOA + 160 + h * 20 + lane] : -INFINITY;
    float mx = logit;
#pragma unroll
    for (int s = 16; s; s >>= 1) mx = fmaxf(mx, __shfl_xor_sync(0xFFFFFFFFu, mx, s));
    float e = (lane < 20) ? __expf(logit - mx) : 0.f;
    float sum = e;
#pragma unroll
    for (int s = 16; s; s >>= 1) sum += __shfl_xor_sync(0xFFFFFFFFu, sum, s);
    float w_sm = e / sum;

    float px = 0.f, py = 0.f;
    if (lane < 20) {
        int l = lane >> 2, p = lane & 3;
        int j = ((h * LL + l) * PP + p) * 2;
        float ox = offaw[(size_t)n * NOA + j];
        float oy = offaw[(size_t)n * NOA + j + 1];
        px = (float)(n & 127) + ox;
        py = (float)(n >> 7) + oy;
    }

    float a0 = 0.f, a1 = 0.f;
    for (int p = 0; p < 20; p++) {
        float x  = __shfl_sync(0xFFFFFFFFu, px, p);
        float y  = __shfl_sync(0xFFFFFFFFu, py, p);
        float wp = __shfl_sync(0xFFFFFFFFu, w_sm, p);
        int l = p >> 2;
        float x0f = floorf(x), y0f = floorf(y);
        float fx = x - x0f, fy = y - y0f;
        int x0 = (int)x0f, y0 = (int)y0f;
        const float* base = val + (size_t)l * NQ * EE + h * HDD + lane * 2;
#pragma unroll
        for (int dy = 0; dy < 2; dy++) {
#pragma unroll
            for (int dx = 0; dx < 2; dx++) {
                int ix = x0 + dx, iy = y0 + dy;
                bool valid = (ix >= 0) & (ix < 128) & (iy >= 0) & (iy < 128);
                float cw = ((dx ? fx : 1.f - fx) * (dy ? fy : 1.f - fy)) * wp;
                cw = valid ? cw : 0.f;
                int cx = min(max(ix, 0), 127);
                int cy = min(max(iy, 0), 127);
                int sidx = cy * 128 + cx;
                float2 gv = *(const float2*)(base + (size_t)sidx * EE);
                a0 += cw * gv.x;
                a1 += cw * gv.y;
            }
        }
    }
    int c0 = h * HDD + lane * 2;
    acc[(size_t)n * EE + permc(c0)]     = f2tf(a0);
    acc[(size_t)n * EE + permc(c0 + 1)] = f2tf(a1);
}

// ---------------- row LayerNorm over E=256 + rounded/permuted copies ----------------
__global__ void ln_kernel(float* __restrict__ x, const float* __restrict__ g,
                          const float* __restrict__ b,
                          float* __restrict__ rOut,
                          const float* __restrict__ pos, float* __restrict__ qpOut) {
    int row = blockIdx.x * 8 + threadIdx.y;
    int lane = threadIdx.x;
    float* xr = x + (size_t)row * 256 + lane * 8;
    float4 v0 = *(const float4*)xr;
    float4 v1 = *(const float4*)(xr + 4);
    float o[8] = {v0.x, v0.y, v0.z, v0.w, v1.x, v1.y, v1.z, v1.w};
    float s = 0.f, q2 = 0.f;
#pragma unroll
    for (int k = 0; k < 8; k++) { s += o[k]; q2 += o[k] * o[k]; }
#pragma unroll
    for (int sh = 16; sh; sh >>= 1) {
        s  += __shfl_xor_sync(0xFFFFFFFFu, s, sh);
        q2 += __shfl_xor_sync(0xFFFFFFFFu, q2, sh);
    }
    float mean = s * (1.f / 256.f);
    float var = q2 * (1.f / 256.f) - mean * mean;
    float rstd = rsqrtf(var + 1e-5f);
    int ecol = lane * 8;
#pragma unroll
    for (int k = 0; k < 8; k++) o[k] = (o[k] - mean) * rstd * g[ecol + k] + b[ecol + k];
    *(float4*)xr       = make_float4(o[0], o[1], o[2], o[3]);
    *(float4*)(xr + 4) = make_float4(o[4], o[5], o[6], o[7]);
    size_t base = (size_t)row * 256 + ecol;
    if (rOut) {
        *(float4*)(rOut + base)     = make_float4(f2tf(o[0]), f2tf(o[4]), f2tf(o[1]), f2tf(o[5]));
        *(float4*)(rOut + base + 4) = make_float4(f2tf(o[2]), f2tf(o[6]), f2tf(o[3]), f2tf(o[7]));
    }
    if (qpOut) {
        float p[8];
        *(float4*)p       = *(const float4*)(pos + base);
        *(float4*)(p + 4) = *(const float4*)(pos + base + 4);
        *(float4*)(qpOut + base)     = make_float4(f2tf(o[0] + p[0]), f2tf(o[4] + p[4]),
                                                   f2tf(o[1] + p[1]), f2tf(o[5] + p[5]));
        *(float4*)(qpOut + base + 4) = make_float4(f2tf(o[2] + p[2]), f2tf(o[6] + p[6]),
                                                   f2tf(o[3] + p[3]), f2tf(o[7] + p[7]));
    }
}

// ---------------- final transpose ----------------
__global__ void transpose_kernel(float* __restrict__ out) {
    __shared__ float t[32][33];
    int n0 = blockIdx.x * 32, e0 = blockIdx.y * 32;
    int tx = threadIdx.x, ty = threadIdx.y;
#pragma unroll
    for (int i = 0; i < 32; i += 8)
        t[ty + i][tx] = g_q[(size_t)(n0 + ty + i) * 256 + e0 + tx];
    __syncthreads();
#pragma unroll
    for (int i = 0; i < 32; i += 8)
        out[(size_t)(e0 + ty + i) * NQ + n0 + tx] = t[tx][ty + i];
}

// ---------------- host orchestration ----------------
extern "C" void kernel_launch(void* const* d_in, const int* in_sizes, int n_in,
                              void* d_out, int out_size) {
    const float* feat   = (const float*)d_in[0];
    const float* n0g    = (const float*)d_in[1];
    const float* n0b    = (const float*)d_in[2];
    const float* in_w   = (const float*)d_in[3];
    const float* in_b   = (const float*)d_in[4];
    const float* prow   = (const float*)d_in[5];
    const float* pcol   = (const float*)d_in[6];
    const float* off_w  = (const float*)d_in[7];
    const float* off_b  = (const float*)d_in[8];
    const float* aw_w   = (const float*)d_in[9];
    const float* aw_b   = (const float*)d_in[10];
    const float* val_w  = (const float*)d_in[11];
    const float* val_b  = (const float*)d_in[12];
    const float* out_w  = (const float*)d_in[13];
    const float* out_b  = (const float*)d_in[14];
    const float* ln1_g  = (const float*)d_in[15];
    const float* ln1_b  = (const float*)d_in[16];
    const float* ln2_g  = (const float*)d_in[17];
    const float* ln2_b  = (const float*)d_in[18];
    const float* ffn_w1 = (const float*)d_in[19];
    const float* ffn_b1 = (const float*)d_in[20];
    const float* ffn_w2 = (const float*)d_in[21];
    const float* ffn_b2 = (const float*)d_in[22];

    float *pf, *pq, *pqr, *pqp, *ppos, *poa, *pval, *pacc, *ph;
    float *pwin, *pwoa, *pwval, *pwout, *pwf1, *pwf2, *pboa;
    cudaGetSymbolAddress((void**)&pf,    g_f);
    cudaGetSymbolAddress((void**)&pq,    g_q);
    cudaGetSymbolAddress((void**)&pqr,   g_qr);
    cudaGetSymbolAddress((void**)&pqp,   g_qp);
    cudaGetSymbolAddress((void**)&ppos,  g_pos);
    cudaGetSymbolAddress((void**)&poa,   g_offaw);
    cudaGetSymbolAddress((void**)&pval,  g_val);
    cudaGetSymbolAddress((void**)&pacc,  g_acc);
    cudaGetSymbolAddress((void**)&ph,    g_h);
    cudaGetSymbolAddress((void**)&pwin,  g_w_in);
    cudaGetSymbolAddress((void**)&pwoa,  g_w_oa);
    cudaGetSymbolAddress((void**)&pwval, g_w_val);
    cudaGetSymbolAddress((void**)&pwout, g_w_out);
    cudaGetSymbolAddress((void**)&pwf1,  g_w_f1);
    cudaGetSymbolAddress((void**)&pwf2,  g_w_f2);
    cudaGetSymbolAddress((void**)&pboa,  g_b_oa);

    cudaFuncSetAttribute(gemm_ca<true, false, false, true>,
                         cudaFuncAttributeMaxDynamicSharedMemorySize, AKM_SMEM);
    cudaFuncSetAttribute(gemm_ca<false, false, false, false>,
                         cudaFuncAttributeMaxDynamicSharedMemorySize, ROW_SMEM);
    cudaFuncSetAttribute(gemm_ca<false, true, true, false>,
                         cudaFuncAttributeMaxDynamicSharedMemorySize, ROW_SMEM);
    cudaFuncSetAttribute(gemm_oaval,
                         cudaFuncAttributeMaxDynamicSharedMemorySize, ROW_SMEM);

    // ---- prologue: round weights, norm0, pos ----
    rcopy5_kernel<<<(NLAY * 256 * 512 + 255) / 256, 256>>>(
        in_w, pwin, 1280 * 256,
        val_w, pwval, NLAY * 256 * 256,
        out_w, pwout, NLAY * 256 * 256,
        ffn_w1, pwf1, NLAY * 256 * 512,
        ffn_w2, pwf2, NLAY * 512 * 256);
    pack_oa_kernel<<<(NLAY * EE * NOA + 255) / 256, 256>>>(off_w, off_b, aw_w, aw_b);
    norm0_kernel<<<dim3(NQ / 256, LL), 256>>>(feat, n0g, n0b);
    pos_kernel<<<NQ, 256>>>(prow, pcol);

    // input_proj: q = f^T @ in_w + in_b; aux qp = tf32(q + pos)
    gemm_ca<true, false, false, true><<<dim3(2, 128), 256, AKM_SMEM>>>(
        pf, pwin, in_b, nullptr, pq, pqp, ppos,
        256, 1280, NQ, (size_t)CC * NQ);

    for (int i = 0; i < NLAY; i++) {
        // merged: z=0 oa (A=qp, N=240); z=1..5 val levels (A=g_f, AKM)
        gemm_oaval<<<dim3(2, 128, 1 + LL), 256, ROW_SMEM>>>(
            pqp, pwoa + (size_t)i * 256 * NOA, pboa + (size_t)i * NOA, poa,
            pf, pwval + (size_t)i * 256 * 256, val_b + (size_t)i * EE, pval);
        // sampling (4 queries x 4 heads per block)
        sample_kernel<<<NQ / 4, dim3(32, 16)>>>(poa, pval, pacc);
        // out proj + residual into q
        gemm_ca<false, false, false, false><<<dim3(2, 128), 256, ROW_SMEM>>>(
            pacc, pwout + (size_t)i * 256 * 256, out_b + (size_t)i * EE, pq,
            pq, nullptr, nullptr, 256, 256, 256, 0);
        ln_kernel<<<NQ / 8, dim3(32, 8)>>>(pq, ln1_g + (size_t)i * EE, ln1_b + (size_t)i * EE,
                                           pqr, nullptr, nullptr);
        // ffn1: relu, output h permuted tf32
        gemm_ca<false, true, true, false><<<dim3(4, 128), 256, ROW_SMEM>>>(
            pqr, pwf1 + (size_t)i * 256 * 512, ffn_b1 + (size_t)i * FFH, nullptr,
            ph, nullptr, nullptr, 512, 256, 256, 0);
        // ffn2 + residual into q
        gemm_ca<false, false, false, false><<<dim3(2, 128), 256, ROW_SMEM>>>(
            ph, pwf2 + (size_t)i * 512 * 256, ffn_b2 + (size_t)i * EE, pq,
            pq, nullptr, nullptr, 256, 512, 512, 0);
        // ln2: writes q fp32 + qp = tf32(q + pos) for next layer
        ln_kernel<<<NQ / 8, dim3(32, 8)>>>(pq, ln2_g + (size_t)i * EE, ln2_b + (size_t)i * EE,
                                           nullptr, ppos, pqp);
    }

    transpose_kernel<<<dim3(NQ / 32, EE / 32), dim3(32, 8)>>>((float*)d_out);
}

// round 11
// speedup vs baseline: 1.0295x; 1.0295x over previous
#include <cuda_runtime.h>
#include <math.h>
#include <stdint.h>

#define NQ 16384
#define CC 256
#define EE 256
#define LL 5
#define NHH 4
#define PP 4
#define HDD 64
#define FFH 512
#define NLAY 6
#define NOA 240

// ---------------- scratch (device globals; no allocation) ----------------
__device__ float g_f[LL * CC * NQ];     // normed features, [l][c][n] K-major, tf32-rounded
__device__ float g_q[NQ * EE];          // query fp32 [n][e]
__device__ float g_qr[NQ * EE];         // permuted tf32 q      (ffn1 A)
__device__ float g_qp[NQ * EE];         // permuted tf32 q+pos  (oa A)
__device__ float g_pos[NQ * EE];
__device__ float g_offaw[NQ * NOA];     // fp32 [n][240]
__device__ float g_val[LL * NQ * EE];   // [l][n][e]
__device__ float g_acc[NQ * EE];        // permuted tf32 (out-proj A)
__device__ float g_h[NQ * FFH];         // permuted tf32 (ffn2 A)
// tf32-rounded weights, [K][N]
__device__ float g_w_in[1280 * 256];
__device__ float g_w_oa[NLAY * 256 * NOA + 64];   // +64 pad for N-tile overrun reads
__device__ float g_w_val[NLAY * 256 * 256];
__device__ float g_w_out[NLAY * 256 * 256];
__device__ float g_w_f1[NLAY * 256 * 512];
__device__ float g_w_f2[NLAY * 512 * 256];
__device__ float g_b_oa[NLAY * NOA];

// ---------------- helpers ----------------
__device__ __forceinline__ float f2tf(float x) {
    unsigned u;
    asm("cvt.rna.tf32.f32 %0, %1;" : "=r"(u) : "f"(x));
    return __uint_as_float(u);
}
__device__ __forceinline__ uint32_t smem_u32(const void* p) {
    uint32_t a;
    asm("{ .reg .u64 t; cvta.to.shared.u64 t, %1; cvt.u32.u64 %0, t; }" : "=r"(a) : "l"(p));
    return a;
}
// column permutation within aligned 8-groups: k -> (k&3)*2 + (k>>2)
__device__ __forceinline__ int permc(int c) {
    return (c & ~7) | (((c & 3) << 1) | ((c >> 2) & 1));
}
__device__ __forceinline__ void mma_tf32(float* cc, const unsigned* a, const unsigned* b) {
    asm volatile(
        "mma.sync.aligned.m16n8k8.row.col.f32.tf32.tf32.f32 "
        "{%0,%1,%2,%3}, {%4,%5,%6,%7}, {%8,%9}, {%0,%1,%2,%3};\n"
        : "+f"(cc[0]), "+f"(cc[1]), "+f"(cc[2]), "+f"(cc[3])
        : "r"(a[0]), "r"(a[1]), "r"(a[2]), "r"(a[3]), "r"(b[0]), "r"(b[1]));
}
#define CPA16(sa, ga) asm volatile("cp.async.cg.shared.global [%0], [%1], 16;" :: "r"(sa), "l"(ga) : "memory")
#define CPA_COMMIT()  asm volatile("cp.async.commit_group;" ::: "memory")
#define CPA_WAIT(n)   asm volatile("cp.async.wait_group %0;" :: "n"(n) : "memory")

// ---------------- prologue kernels ----------------
__global__ void rcopy5_kernel(const float* __restrict__ s0, float* __restrict__ d0, int n0,
                              const float* __restrict__ s1, float* __restrict__ d1, int n1,
                              const float* __restrict__ s2, float* __restrict__ d2, int n2,
                              const float* __restrict__ s3, float* __restrict__ d3, int n3,
                              const float* __restrict__ s4, float* __restrict__ d4, int n4) {
    int i = blockIdx.x * 256 + threadIdx.x;
    if (i < n0) d0[i] = f2tf(s0[i]);
    if (i < n1) d1[i] = f2tf(s1[i]);
    if (i < n2) d2[i] = f2tf(s2[i]);
    if (i < n3) d3[i] = f2tf(s3[i]);
    if (i < n4) d4[i] = f2tf(s4[i]);
}

__global__ void pack_oa_kernel(const float* __restrict__ off_w, const float* __restrict__ off_b,
                               const float* __restrict__ aw_w, const float* __restrict__ aw_b) {
    int idx = blockIdx.x * 256 + threadIdx.x;
    if (idx >= NLAY * EE * NOA) return;
    int c = idx % NOA;
    int e = (idx / NOA) % EE;
    int i = idx / (NOA * EE);
    float v = (c < 160) ? off_w[((size_t)i * EE + e) * 160 + c]
                        : aw_w[((size_t)i * EE + e) * 80 + (c - 160)];
    g_w_oa[idx] = f2tf(v);
    if (e == 0)
        g_b_oa[i * NOA + c] = (c < 160) ? off_b[i * 160 + c] : aw_b[i * 80 + (c - 160)];
}

__global__ void norm0_kernel(const float* __restrict__ feat,
                             const float* __restrict__ g,
                             const float* __restrict__ b) {
    int n = blockIdx.x * blockDim.x + threadIdx.x;
    int l = blockIdx.y;
    const float* src = feat + (size_t)l * CC * NQ + n;
    float sum = 0.f, sq = 0.f;
#pragma unroll 8
    for (int c = 0; c < CC; c++) {
        float v = src[(size_t)c * NQ];
        sum += v; sq += v * v;
    }
    float mean = sum * (1.f / CC);
    float var = sq * (1.f / CC) - mean * mean;
    float rstd = rsqrtf(var + 1e-5f);
    float* dst = g_f + (size_t)l * CC * NQ + n;
#pragma unroll 8
    for (int c = 0; c < CC; c++)
        dst[(size_t)c * NQ] = f2tf((src[(size_t)c * NQ] - mean) * rstd * g[l * CC + c] + b[l * CC + c]);
}

__global__ void pos_kernel(const float* __restrict__ prow, const float* __restrict__ pcol) {
    int i = blockIdx.x * 256 + threadIdx.x;
    int n = i >> 8, e = i & 255;
    int hh = n >> 7, ww = n & 127;
    g_pos[i] = (e < 128) ? pcol[ww * 128 + e] : prow[hh * 128 + (e - 128)];
}

// ---------------- tf32 tensor-core GEMM, cp.async 4-stage pipeline ----------------
#define APAD 24
#define BPAD 136
#define STAGES 4
#define ROW_SMEM (STAGES * (128 * APAD + 16 * BPAD) * 4)
#define AKM_SMEM (STAGES * (16 * BPAD + 16 * BPAD) * 4)

template <bool AKM, bool RELU, bool ROUNDC, bool AUXQP>
__global__ void __launch_bounds__(256, 2) gemm_ca(
    const float* __restrict__ A, const float* __restrict__ B,
    const float* __restrict__ bias, const float* __restrict__ resid,
    float* __restrict__ C, float* __restrict__ Caux, const float* __restrict__ Pos,
    int M, int N, int K, int lda, size_t aBlockStride,
    size_t aZ, size_t cZ) {
    extern __shared__ __align__(16) char sraw[];
    constexpr int ASF = AKM ? (16 * BPAD) : (128 * APAD);
    constexpr int BSF = 16 * BPAD;
    float* AsBase = (float*)sraw;
    float* BsBase = (float*)sraw + STAGES * ASF;

    const int tid = threadIdx.x;
    const int warp = tid >> 5, lane = tid & 31;
    const int m0 = blockIdx.y * 128, n0 = blockIdx.x * 128;
    A += blockIdx.z * aZ;
    C += blockIdx.z * cZ;
    const int wm = (warp & 3) * 32, wn = (warp >> 2) * 64;
    const int r = lane >> 2, cq = lane & 3;

    const uint32_t uA = smem_u32(AsBase);
    const uint32_t uB = smem_u32(BsBase);
    const int KT = K >> 4;

    float acc[2][8][4];
#pragma unroll
    for (int mt = 0; mt < 2; mt++)
#pragma unroll
        for (int nt = 0; nt < 8; nt++)
#pragma unroll
            for (int k = 0; k < 4; k++) acc[mt][nt][k] = 0.f;

    auto ld_stage = [&](int kt) {
        int st = kt & (STAGES - 1);
        int kk = kt << 4;
        if (AKM) {
            int blk = kk >> 8;
            int kin = kk & 255;
            const float* base = A + (size_t)blk * aBlockStride;
#pragma unroll
            for (int t = 0; t < 2; t++) {
                int ch = tid + t * 256;
                int j = ch >> 5, co = (ch & 31) << 2;
                CPA16(uA + (uint32_t)(st * ASF + j * BPAD + co) * 4,
                      base + (size_t)(kin + j) * lda + m0 + co);
            }
        } else {
#pragma unroll
            for (int t = 0; t < 2; t++) {
                int ch = tid + t * 256;
                int i = ch >> 2, kc = (ch & 3) << 2;
                CPA16(uA + (uint32_t)(st * ASF + i * APAD + kc) * 4,
                      A + (size_t)(m0 + i) * lda + kk + kc);
            }
        }
#pragma unroll
        for (int t = 0; t < 2; t++) {
            int ch = tid + t * 256;
            int j = ch >> 5, co = (ch & 31) << 2;
            CPA16(uB + (uint32_t)(st * BSF + j * BPAD + co) * 4,
                  B + (size_t)(kk + j) * N + n0 + co);
        }
    };

#pragma unroll
    for (int s = 0; s < STAGES - 1; s++) { ld_stage(s); CPA_COMMIT(); }

    for (int kt = 0; kt < KT; kt++) {
        CPA_WAIT(STAGES - 2);
        __syncthreads();
        if (kt + STAGES - 1 < KT) ld_stage(kt + STAGES - 1);
        CPA_COMMIT();

        const float* a_s = AsBase + (kt & (STAGES - 1)) * ASF;
        const float* b_s = BsBase + (kt & (STAGES - 1)) * BSF;
#pragma unroll
        for (int k8 = 0; k8 < 16; k8 += 8) {
            unsigned af[2][4], bf[8][2];
            if (AKM) {
#pragma unroll
                for (int mt = 0; mt < 2; mt++) {
                    int mb = wm + mt * 16 + r;
                    af[mt][0] = ((const unsigned*)a_s)[(k8 + cq) * BPAD + mb];
                    af[mt][1] = ((const unsigned*)a_s)[(k8 + cq) * BPAD + mb + 8];
                    af[mt][2] = ((const unsigned*)a_s)[(k8 + cq + 4) * BPAD + mb];
                    af[mt][3] = ((const unsigned*)a_s)[(k8 + cq + 4) * BPAD + mb + 8];
                }
            } else {
#pragma unroll
                for (int mt = 0; mt < 2; mt++) {
                    int mb = wm + mt * 16 + r;
                    float2 p0 = *(const float2*)(a_s + mb * APAD + k8 + 2 * cq);
                    float2 p1 = *(const float2*)(a_s + (mb + 8) * APAD + k8 + 2 * cq);
                    af[mt][0] = __float_as_uint(p0.x);
                    af[mt][1] = __float_as_uint(p1.x);
                    af[mt][2] = __float_as_uint(p0.y);
                    af[mt][3] = __float_as_uint(p1.y);
                }
            }
#pragma unroll
            for (int nt = 0; nt < 8; nt++) {
                int nb = wn + nt * 8 + r;
                bf[nt][0] = ((const unsigned*)b_s)[(k8 + cq) * BPAD + nb];
                bf[nt][1] = ((const unsigned*)b_s)[(k8 + cq + 4) * BPAD + nb];
            }
#pragma unroll
            for (int mt = 0; mt < 2; mt++)
#pragma unroll
                for (int nt = 0; nt < 8; nt++)
                    mma_tf32(acc[mt][nt], af[mt], bf[nt]);
        }
    }

    // ---- epilogue ----
#pragma unroll
    for (int mt = 0; mt < 2; mt++) {
#pragma unroll
        for (int nt = 0; nt < 8; nt++) {
            int row = m0 + wm + mt * 16 + r;
            int col = n0 + wn + nt * 8 + 2 * cq;
            if (col < N) {
                float b0 = bias[col], b1 = bias[col + 1];
#pragma unroll
                for (int hh = 0; hh < 2; hh++) {
                    int rr = row + hh * 8;
                    float v0 = acc[mt][nt][hh * 2 + 0] + b0;
                    float v1 = acc[mt][nt][hh * 2 + 1] + b1;
                    if (resid) {
                        float2 rv = *(const float2*)(resid + (size_t)rr * N + col);
                        v0 += rv.x; v1 += rv.y;
                    }
                    if (RELU) { v0 = fmaxf(v0, 0.f); v1 = fmaxf(v1, 0.f); }
                    if (ROUNDC) {
                        C[(size_t)rr * N + permc(col)]     = f2tf(v0);
                        C[(size_t)rr * N + permc(col + 1)] = f2tf(v1);
                    } else {
                        *(float2*)(C + (size_t)rr * N + col) = make_float2(v0, v1);
                        if (AUXQP) {
                            float p0 = Pos[(size_t)rr * 256 + col];
                            float p1 = Pos[(size_t)rr * 256 + col + 1];
                            Caux[(size_t)rr * 256 + permc(col)]     = f2tf(v0 + p0);
                            Caux[(size_t)rr * 256 + permc(col + 1)] = f2tf(v1 + p1);
                        }
                    }
                }
            }
        }
    }
}

// ---------------- fused softmax + bilinear deformable sampling ----------------
// grid NQ/4 blocks, block (32,16): 16 warps = 4 adjacent queries x 4 heads.
__global__ void __launch_bounds__(512) sample_kernel(
        const float* __restrict__ offaw,
        const float* __restrict__ val,
        float* __restrict__ acc) {
    int w = threadIdx.y;
    int n = blockIdx.x * 4 + (w >> 2);
    int h = w & 3;
    int lane = threadIdx.x;

    float logit = (lane < 20) ? offaw[(size_t)n * NOA + 160 + h * 20 + lane] : -INFINITY;
    float mx = logit;
#pragma unroll
    for (int s = 16; s; s >>= 1) mx = fmaxf(mx, __shfl_xor_sync(0xFFFFFFFFu, mx, s));
    float e = (lane < 20) ? __expf(logit - mx) : 0.f;
    float sum = e;
#pragma unroll
    for (int s = 16; s; s >>= 1) sum += __shfl_xor_sync(0xFFFFFFFFu, sum, s);
    float w_sm = e / sum;

    float px = 0.f, py = 0.f;
    if (lane < 20) {
        int l = lane >> 2, p = lane & 3;
        int j = ((h * LL + l) * PP + p) * 2;
        float ox = offaw[(size_t)n * NOA + j];
        float oy = offaw[(size_t)n * NOA + j + 1];
        px = (float)(n & 127) + ox;
        py = (float)(n >> 7) + oy;
    }

    float a0 = 0.f, a1 = 0.f;
    // unroll 4: batches 16 independent gathers in flight per lane; l = p>>2 constant
    // within each group of 4 (one level), so the level base pointer strength-reduces.
#pragma unroll 4
    for (int p = 0; p < 20; p++) {
        float x  = __shfl_sync(0xFFFFFFFFu, px, p);
        float y  = __shfl_sync(0xFFFFFFFFu, py, p);
        float wp = __shfl_sync(0xFFFFFFFFu, w_sm, p);
        int l = p >> 2;
        float x0f = floorf(x), y0f = floorf(y);
        float fx = x - x0f, fy = y - y0f;
        int x0 = (int)x0f, y0 = (int)y0f;
        const float* base = val + (size_t)l * NQ * EE + h * HDD + lane * 2;
#pragma unroll
        for (int dy = 0; dy < 2; dy++) {
#pragma unroll
            for (int dx = 0; dx < 2; dx++) {
                int ix = x0 + dx, iy = y0 + dy;
                bool valid = (ix >= 0) & (ix < 128) & (iy >= 0) & (iy < 128);
                float cw = ((dx ? fx : 1.f - fx) * (dy ? fy : 1.f - fy)) * wp;
                cw = valid ? cw : 0.f;
                int cx = min(max(ix, 0), 127);
                int cy = min(max(iy, 0), 127);
                int sidx = cy * 128 + cx;
                float2 gv = *(const float2*)(base + (size_t)sidx * EE);
                a0 += cw * gv.x;
                a1 += cw * gv.y;
            }
        }
    }
    int c0 = h * HDD + lane * 2;
    acc[(size_t)n * EE + permc(c0)]     = f2tf(a0);
    acc[(size_t)n * EE + permc(c0 + 1)] = f2tf(a1);
}

// ---------------- row LayerNorm over E=256 + rounded/permuted copies ----------------
__global__ void ln_kernel(float* __restrict__ x, const float* __restrict__ g,
                          const float* __restrict__ b,
                          float* __restrict__ rOut,
                          const float* __restrict__ pos, float* __restrict__ qpOut) {
    int row = blockIdx.x * 8 + threadIdx.y;
    int lane = threadIdx.x;
    float* xr = x + (size_t)row * 256 + lane * 8;
    float4 v0 = *(const float4*)xr;
    float4 v1 = *(const float4*)(xr + 4);
    float o[8] = {v0.x, v0.y, v0.z, v0.w, v1.x, v1.y, v1.z, v1.w};
    float s = 0.f, q2 = 0.f;
#pragma unroll
    for (int k = 0; k < 8; k++) { s += o[k]; q2 += o[k] * o[k]; }
#pragma unroll
    for (int sh = 16; sh; sh >>= 1) {
        s  += __shfl_xor_sync(0xFFFFFFFFu, s, sh);
        q2 += __shfl_xor_sync(0xFFFFFFFFu, q2, sh);
    }
    float mean = s * (1.f / 256.f);
    float var = q2 * (1.f / 256.f) - mean * mean;
    float rstd = rsqrtf(var + 1e-5f);
    int ecol = lane * 8;
#pragma unroll
    for (int k = 0; k < 8; k++) o[k] = (o[k] - mean) * rstd * g[ecol + k] + b[ecol + k];
    *(float4*)xr       = make_float4(o[0], o[1], o[2], o[3]);
    *(float4*)(xr + 4) = make_float4(o[4], o[5], o[6], o[7]);
    size_t base = (size_t)row * 256 + ecol;
    if (rOut) {
        *(float4*)(rOut + base)     = make_float4(f2tf(o[0]), f2tf(o[4]), f2tf(o[1]), f2tf(o[5]));
        *(float4*)(rOut + base + 4) = make_float4(f2tf(o[2]), f2tf(o[6]), f2tf(o[3]), f2tf(o[7]));
    }
    if (qpOut) {
        float p[8];
        *(float4*)p       = *(const float4*)(pos + base);
        *(float4*)(p + 4) = *(const float4*)(pos + base + 4);
        *(float4*)(qpOut + base)     = make_float4(f2tf(o[0] + p[0]), f2tf(o[4] + p[4]),
                                                   f2tf(o[1] + p[1]), f2tf(o[5] + p[5]));
        *(float4*)(qpOut + base + 4) = make_float4(f2tf(o[2] + p[2]), f2tf(o[6] + p[6]),
                                                   f2tf(o[3] + p[3]), f2tf(o[7] + p[7]));
    }
}

// ---------------- final transpose ----------------
__global__ void transpose_kernel(float* __restrict__ out) {
    __shared__ float t[32][33];
    int n0 = blockIdx.x * 32, e0 = blockIdx.y * 32;
    int tx = threadIdx.x, ty = threadIdx.y;
#pragma unroll
    for (int i = 0; i < 32; i += 8)
        t[ty + i][tx] = g_q[(size_t)(n0 + ty + i) * 256 + e0 + tx];
    __syncthreads();
#pragma unroll
    for (int i = 0; i < 32; i += 8)
        out[(size_t)(e0 + ty + i) * NQ + n0 + tx] = t[tx][ty + i];
}

// ---------------- host orchestration ----------------
extern "C" void kernel_launch(void* const* d_in, const int* in_sizes, int n_in,
                              void* d_out, int out_size) {
    const float* feat   = (const float*)d_in[0];
    const float* n0g    = (const float*)d_in[1];
    const float* n0b    = (const float*)d_in[2];
    const float* in_w   = (const float*)d_in[3];
    const float* in_b   = (const float*)d_in[4];
    const float* prow   = (const float*)d_in[5];
    const float* pcol   = (const float*)d_in[6];
    const float* off_w  = (const float*)d_in[7];
    const float* off_b  = (const float*)d_in[8];
    const float* aw_w   = (const float*)d_in[9];
    const float* aw_b   = (const float*)d_in[10];
    const float* val_w  = (const float*)d_in[11];
    const float* val_b  = (const float*)d_in[12];
    const float* out_w  = (const float*)d_in[13];
    const float* out_b  = (const float*)d_in[14];
    const float* ln1_g  = (const float*)d_in[15];
    const float* ln1_b  = (const float*)d_in[16];
    const float* ln2_g  = (const float*)d_in[17];
    const float* ln2_b  = (const float*)d_in[18];
    const float* ffn_w1 = (const float*)d_in[19];
    const float* ffn_b1 = (const float*)d_in[20];
    const float* ffn_w2 = (const float*)d_in[21];
    const float* ffn_b2 = (const float*)d_in[22];

    float *pf, *pq, *pqr, *pqp, *ppos, *poa, *pval, *pacc, *ph;
    float *pwin, *pwoa, *pwval, *pwout, *pwf1, *pwf2, *pboa;
    cudaGetSymbolAddress((void**)&pf,    g_f);
    cudaGetSymbolAddress((void**)&pq,    g_q);
    cudaGetSymbolAddress((void**)&pqr,   g_qr);
    cudaGetSymbolAddress((void**)&pqp,   g_qp);
    cudaGetSymbolAddress((void**)&ppos,  g_pos);
    cudaGetSymbolAddress((void**)&poa,   g_offaw);
    cudaGetSymbolAddress((void**)&pval,  g_val);
    cudaGetSymbolAddress((void**)&pacc,  g_acc);
    cudaGetSymbolAddress((void**)&ph,    g_h);
    cudaGetSymbolAddress((void**)&pwin,  g_w_in);
    cudaGetSymbolAddress((void**)&pwoa,  g_w_oa);
    cudaGetSymbolAddress((void**)&pwval, g_w_val);
    cudaGetSymbolAddress((void**)&pwout, g_w_out);
    cudaGetSymbolAddress((void**)&pwf1,  g_w_f1);
    cudaGetSymbolAddress((void**)&pwf2,  g_w_f2);
    cudaGetSymbolAddress((void**)&pboa,  g_b_oa);

    cudaFuncSetAttribute(gemm_ca<true, false, false, true>,
                         cudaFuncAttributeMaxDynamicSharedMemorySize, AKM_SMEM);
    cudaFuncSetAttribute(gemm_ca<true, false, false, false>,
                         cudaFuncAttributeMaxDynamicSharedMemorySize, AKM_SMEM);
    cudaFuncSetAttribute(gemm_ca<false, false, false, false>,
                         cudaFuncAttributeMaxDynamicSharedMemorySize, ROW_SMEM);
    cudaFuncSetAttribute(gemm_ca<false, true, true, false>,
                         cudaFuncAttributeMaxDynamicSharedMemorySize, ROW_SMEM);

    // ---- prologue: round weights (one batched launch), norm0, pos ----
    rcopy5_kernel<<<(NLAY * 256 * 512 + 255) / 256, 256>>>(
        in_w, pwin, 1280 * 256,
        val_w, pwval, NLAY * 256 * 256,
        out_w, pwout, NLAY * 256 * 256,
        ffn_w1, pwf1, NLAY * 256 * 512,
        ffn_w2, pwf2, NLAY * 512 * 256);
    pack_oa_kernel<<<(NLAY * EE * NOA + 255) / 256, 256>>>(off_w, off_b, aw_w, aw_b);
    norm0_kernel<<<dim3(NQ / 256, LL), 256>>>(feat, n0g, n0b);
    pos_kernel<<<NQ, 256>>>(prow, pcol);

    // input_proj: q = f^T @ in_w + in_b; aux qp = tf32(q + pos)
    gemm_ca<true, false, false, true><<<dim3(2, 128), 256, AKM_SMEM>>>(
        pf, pwin, in_b, nullptr, pq, pqp, ppos,
        NQ, 256, 1280, NQ, (size_t)CC * NQ, 0, 0);

    for (int i = 0; i < NLAY; i++) {
        // offsets + aw logits (N=240), A = qp (permuted tf32)
        gemm_ca<false, false, false, false><<<dim3(2, 128), 256, ROW_SMEM>>>(
            pqp, pwoa + (size_t)i * 256 * NOA, pboa + (size_t)i * NOA, nullptr,
            poa, nullptr, nullptr, NQ, NOA, 256, 256, 0, 0, 0);
        // val projection, 5 levels via grid.z, A = g_f (K-major)
        gemm_ca<true, false, false, false><<<dim3(2, 128, LL), 256, AKM_SMEM>>>(
            pf, pwval + (size_t)i * 256 * 256, val_b + (size_t)i * EE, nullptr,
            pval, nullptr, nullptr, NQ, 256, 256, NQ, 0,
            (size_t)CC * NQ, (size_t)NQ * EE);
        // sampling (4 queries x 4 heads per block)
        sample_kernel<<<NQ / 4, dim3(32, 16)>>>(poa, pval, pacc);
        // out proj + residual into q
        gemm_ca<false, false, false, false><<<dim3(2, 128), 256, ROW_SMEM>>>(
            pacc, pwout + (size_t)i * 256 * 256, out_b + (size_t)i * EE, pq,
            pq, nullptr, nullptr, NQ, 256, 256, 256, 0, 0, 0);
        ln_kernel<<<NQ / 8, dim3(32, 8)>>>(pq, ln1_g + (size_t)i * EE, ln1_b + (size_t)i * EE,
                                           pqr, nullptr, nullptr);
        // ffn1: relu, output h permuted tf32
        gemm_ca<false, true, true, false><<<dim3(4, 128), 256, ROW_SMEM>>>(
            pqr, pwf1 + (size_t)i * 256 * 512, ffn_b1 + (size_t)i * FFH, nullptr,
            ph, nullptr, nullptr, NQ, 512, 256, 256, 0, 0, 0);
        // ffn2 + residual into q
        gemm_ca<false, false, false, false><<<dim3(2, 128), 256, ROW_SMEM>>>(
            ph, pwf2 + (size_t)i * 512 * 256, ffn_b2 + (size_t)i * EE, pq,
            pq, nullptr, nullptr, NQ, 256, 512, 512, 0, 0, 0);
        // ln2: writes q fp32 + qp = tf32(q + pos) for next layer
        ln_kernel<<<NQ / 8, dim3(32, 8)>>>(pq, ln2_g + (size_t)i * EE, ln2_b + (size_t)i * EE,
                                           nullptr, ppos, pqp);
    }

    transpose_kernel<<<dim3(NQ / 32, EE / 32), dim3(32, 8)>>>((float*)d_out);
}

// round 13
// speedup vs baseline: 1.1411x; 1.1085x over previous
#include <cuda_runtime.h>
#include <math.h>
#include <stdint.h>

#define NQ 16384
#define CC 256
#define EE 256
#define LL 5
#define NHH 4
#define PP 4
#define HDD 64
#define FFH 512
#define NLAY 6
#define NOA 240

// ---------------- scratch (device globals; no allocation) ----------------
__device__ float g_f[LL * CC * NQ];     // normed features, [l][c][n] K-major, tf32-rounded
__device__ float g_q[NQ * EE];          // query fp32 [n][e]
__device__ float g_qr[NQ * EE];         // permuted tf32 q      (ffn1 A)
__device__ float g_qp[NQ * EE];         // permuted tf32 q+pos  (oa A)
__device__ float g_offaw[NQ * NOA];     // fp32 [n][240]
__device__ float g_val[LL * NQ * EE];   // [l][n][e]
__device__ float g_acc[NQ * EE];        // permuted tf32 (out-proj A)
__device__ float g_h[NQ * FFH];         // permuted tf32 (ffn2 A)
// tf32-rounded weights, [K][N]
__device__ float g_w_in[1280 * 256];
__device__ float g_w_oa[NLAY * 256 * NOA + 64];   // +64 pad for N-tile overrun reads
__device__ float g_w_val[NLAY * 256 * 256];
__device__ float g_w_out[NLAY * 256 * 256];
__device__ float g_w_f1[NLAY * 256 * 512];
__device__ float g_w_f2[NLAY * 512 * 256];
__device__ float g_b_oa[NLAY * NOA];

// ---------------- helpers ----------------
__device__ __forceinline__ float f2tf(float x) {
    unsigned u;
    asm("cvt.rna.tf32.f32 %0, %1;" : "=r"(u) : "f"(x));
    return __uint_as_float(u);
}
__device__ __forceinline__ uint32_t smem_u32(const void* p) {
    uint32_t a;
    asm("{ .reg .u64 t; cvta.to.shared.u64 t, %1; cvt.u32.u64 %0, t; }" : "=r"(a) : "l"(p));
    return a;
}
// column permutation within aligned 8-groups: k -> (k&3)*2 + (k>>2)
__device__ __forceinline__ int permc(int c) {
    return (c & ~7) | (((c & 3) << 1) | ((c >> 2) & 1));
}
__device__ __forceinline__ void mma_tf32(float* cc, const unsigned* a, const unsigned* b) {
    asm volatile(
        "mma.sync.aligned.m16n8k8.row.col.f32.tf32.tf32.f32 "
        "{%0,%1,%2,%3}, {%4,%5,%6,%7}, {%8,%9}, {%0,%1,%2,%3};\n"
        : "+f"(cc[0]), "+f"(cc[1]), "+f"(cc[2]), "+f"(cc[3])
        : "r"(a[0]), "r"(a[1]), "r"(a[2]), "r"(a[3]), "r"(b[0]), "r"(b[1]));
}
#define CPA16(sa, ga) asm volatile("cp.async.cg.shared.global [%0], [%1], 16;" :: "r"(sa), "l"(ga) : "memory")
#define CPA_COMMIT()  asm volatile("cp.async.commit_group;" ::: "memory")
#define CPA_WAIT(n)   asm volatile("cp.async.wait_group %0;" :: "n"(n) : "memory")

// ---------------- prologue kernels ----------------
__global__ void rcopy5_kernel(const float* __restrict__ s0, float* __restrict__ d0, int n0,
                              const float* __restrict__ s1, float* __restrict__ d1, int n1,
                              const float* __restrict__ s2, float* __restrict__ d2, int n2,
                              const float* __restrict__ s3, float* __restrict__ d3, int n3,
                              const float* __restrict__ s4, float* __restrict__ d4, int n4) {
    int i = blockIdx.x * 256 + threadIdx.x;
    if (i < n0) d0[i] = f2tf(s0[i]);
    if (i < n1) d1[i] = f2tf(s1[i]);
    if (i < n2) d2[i] = f2tf(s2[i]);
    if (i < n3) d3[i] = f2tf(s3[i]);
    if (i < n4) d4[i] = f2tf(s4[i]);
}

__global__ void pack_oa_kernel(const float* __restrict__ off_w, const float* __restrict__ off_b,
                               const float* __restrict__ aw_w, const float* __restrict__ aw_b) {
    int idx = blockIdx.x * 256 + threadIdx.x;
    if (idx >= NLAY * EE * NOA) return;
    int c = idx % NOA;
    int e = (idx / NOA) % EE;
    int i = idx / (NOA * EE);
    float v = (c < 160) ? off_w[((size_t)i * EE + e) * 160 + c]
                        : aw_w[((size_t)i * EE + e) * 80 + (c - 160)];
    g_w_oa[idx] = f2tf(v);
    if (e == 0)
        g_b_oa[i * NOA + c] = (c < 160) ? off_b[i * 160 + c] : aw_b[i * 80 + (c - 160)];
}

__global__ void norm0_kernel(const float* __restrict__ feat,
                             const float* __restrict__ g,
                             const float* __restrict__ b) {
    int n = blockIdx.x * blockDim.x + threadIdx.x;
    int l = blockIdx.y;
    const float* src = feat + (size_t)l * CC * NQ + n;
    float sum = 0.f, sq = 0.f;
#pragma unroll 8
    for (int c = 0; c < CC; c++) {
        float v = src[(size_t)c * NQ];
        sum += v; sq += v * v;
    }
    float mean = sum * (1.f / CC);
    float var = sq * (1.f / CC) - mean * mean;
    float rstd = rsqrtf(var + 1e-5f);
    float* dst = g_f + (size_t)l * CC * NQ + n;
#pragma unroll 8
    for (int c = 0; c < CC; c++)
        dst[(size_t)c * NQ] = f2tf((src[(size_t)c * NQ] - mean) * rstd * g[l * CC + c] + b[l * CC + c]);
}

// ---------------- tf32 tensor-core GEMM, cp.async 4-stage pipeline ----------------
#define APAD 24
#define BPAD 136
#define STAGES 4
#define ROW_SMEM (STAGES * (128 * APAD + 16 * BPAD) * 4)
#define AKM_SMEM (STAGES * (16 * BPAD + 16 * BPAD) * 4)

template <bool AKM, bool RELU, bool ROUNDC, bool AUXQP>
__global__ void __launch_bounds__(256, 2) gemm_ca(
    const float* __restrict__ A, const float* __restrict__ B,
    const float* __restrict__ bias, const float* __restrict__ resid,
    float* __restrict__ C, float* __restrict__ Caux,
    const float* __restrict__ Prow, const float* __restrict__ Pcol,
    int M, int N, int K, int lda, size_t aBlockStride,
    size_t aZ, size_t cZ) {
    extern __shared__ __align__(16) char sraw[];
    constexpr int ASF = AKM ? (16 * BPAD) : (128 * APAD);
    constexpr int BSF = 16 * BPAD;
    float* AsBase = (float*)sraw;
    float* BsBase = (float*)sraw + STAGES * ASF;

    const int tid = threadIdx.x;
    const int warp = tid >> 5, lane = tid & 31;
    const int m0 = blockIdx.y * 128, n0 = blockIdx.x * 128;
    A += blockIdx.z * aZ;
    C += blockIdx.z * cZ;
    const int wm = (warp & 3) * 32, wn = (warp >> 2) * 64;
    const int r = lane >> 2, cq = lane & 3;

    const uint32_t uA = smem_u32(AsBase);
    const uint32_t uB = smem_u32(BsBase);
    const int KT = K >> 4;

    float acc[2][8][4];
#pragma unroll
    for (int mt = 0; mt < 2; mt++)
#pragma unroll
        for (int nt = 0; nt < 8; nt++)
#pragma unroll
            for (int k = 0; k < 4; k++) acc[mt][nt][k] = 0.f;

    auto ld_stage = [&](int kt) {
        int st = kt & (STAGES - 1);
        int kk = kt << 4;
        if (AKM) {
            int blk = kk >> 8;
            int kin = kk & 255;
            const float* base = A + (size_t)blk * aBlockStride;
#pragma unroll
            for (int t = 0; t < 2; t++) {
                int ch = tid + t * 256;
                int j = ch >> 5, co = (ch & 31) << 2;
                CPA16(uA + (uint32_t)(st * ASF + j * BPAD + co) * 4,
                      base + (size_t)(kin + j) * lda + m0 + co);
            }
        } else {
#pragma unroll
            for (int t = 0; t < 2; t++) {
                int ch = tid + t * 256;
                int i = ch >> 2, kc = (ch & 3) << 2;
                CPA16(uA + (uint32_t)(st * ASF + i * APAD + kc) * 4,
                      A + (size_t)(m0 + i) * lda + kk + kc);
            }
        }
#pragma unroll
        for (int t = 0; t < 2; t++) {
            int ch = tid + t * 256;
            int j = ch >> 5, co = (ch & 31) << 2;
            CPA16(uB + (uint32_t)(st * BSF + j * BPAD + co) * 4,
                  B + (size_t)(kk + j) * N + n0 + co);
        }
    };

#pragma unroll
    for (int s = 0; s < STAGES - 1; s++) { ld_stage(s); CPA_COMMIT(); }

    for (int kt = 0; kt < KT; kt++) {
        CPA_WAIT(STAGES - 2);
        __syncthreads();
        if (kt + STAGES - 1 < KT) ld_stage(kt + STAGES - 1);
        CPA_COMMIT();

        const float* a_s = AsBase + (kt & (STAGES - 1)) * ASF;
        const float* b_s = BsBase + (kt & (STAGES - 1)) * BSF;
#pragma unroll
        for (int k8 = 0; k8 < 16; k8 += 8) {
            unsigned af[2][4], bf[8][2];
            if (AKM) {
#pragma unroll
                for (int mt = 0; mt < 2; mt++) {
                    int mb = wm + mt * 16 + r;
                    af[mt][0] = ((const unsigned*)a_s)[(k8 + cq) * BPAD + mb];
                    af[mt][1] = ((const unsigned*)a_s)[(k8 + cq) * BPAD + mb + 8];
                    af[mt][2] = ((const unsigned*)a_s)[(k8 + cq + 4) * BPAD + mb];
                    af[mt][3] = ((const unsigned*)a_s)[(k8 + cq + 4) * BPAD + mb + 8];
                }
            } else {
#pragma unroll
                for (int mt = 0; mt < 2; mt++) {
                    int mb = wm + mt * 16 + r;
                    float2 p0 = *(const float2*)(a_s + mb * APAD + k8 + 2 * cq);
                    float2 p1 = *(const float2*)(a_s + (mb + 8) * APAD + k8 + 2 * cq);
                    af[mt][0] = __float_as_uint(p0.x);
                    af[mt][1] = __float_as_uint(p1.x);
                    af[mt][2] = __float_as_uint(p0.y);
                    af[mt][3] = __float_as_uint(p1.y);
                }
            }
#pragma unroll
            for (int nt = 0; nt < 8; nt++) {
                int nb = wn + nt * 8 + r;
                bf[nt][0] = ((const unsigned*)b_s)[(k8 + cq) * BPAD + nb];
                bf[nt][1] = ((const unsigned*)b_s)[(k8 + cq + 4) * BPAD + nb];
            }
#pragma unroll
            for (int mt = 0; mt < 2; mt++)
#pragma unroll
                for (int nt = 0; nt < 8; nt++)
                    mma_tf32(acc[mt][nt], af[mt], bf[nt]);
        }
    }

    // ---- epilogue ----
#pragma unroll
    for (int mt = 0; mt < 2; mt++) {
#pragma unroll
        for (int nt = 0; nt < 8; nt++) {
            int row = m0 + wm + mt * 16 + r;
            int col = n0 + wn + nt * 8 + 2 * cq;
            if (col < N) {
                float b0 = bias[col], b1 = bias[col + 1];
#pragma unroll
                for (int hh = 0; hh < 2; hh++) {
                    int rr = row + hh * 8;
                    float v0 = acc[mt][nt][hh * 2 + 0] + b0;
                    float v1 = acc[mt][nt][hh * 2 + 1] + b1;
                    if (resid) {
                        float2 rv = *(const float2*)(resid + (size_t)rr * N + col);
                        v0 += rv.x; v1 += rv.y;
                    }
                    if (RELU) { v0 = fmaxf(v0, 0.f); v1 = fmaxf(v1, 0.f); }
                    if (ROUNDC) {
                        C[(size_t)rr * N + permc(col)]     = f2tf(v0);
                        C[(size_t)rr * N + permc(col + 1)] = f2tf(v1);
                    } else {
                        *(float2*)(C + (size_t)rr * N + col) = make_float2(v0, v1);
                        if (AUXQP) {
                            // pos computed on the fly: e<128 -> pcol[w][e], else prow[h][e-128]
                            int ww = rr & 127, hr = rr >> 7;
                            float p0, p1;
                            if (col < 128) {
                                p0 = Pcol[ww * 128 + col];
                                p1 = Pcol[ww * 128 + col + 1];
                            } else {
                                p0 = Prow[hr * 128 + col - 128];
                                p1 = Prow[hr * 128 + col - 127];
                            }
                            Caux[(size_t)rr * 256 + permc(col)]     = f2tf(v0 + p0);
                            Caux[(size_t)rr * 256 + permc(col + 1)] = f2tf(v1 + p1);
                        }
                    }
                }
            }
        }
    }
}

// ---------------- fused softmax + bilinear deformable sampling ----------------
// grid NQ/4 blocks, block (32,16): warp = (query, head).
// Gather phase: half-warp point-split — lanes 0-15 do points 0-9, lanes 16-31 do
// points 10-19; each lane loads a float4 (16 lanes cover the 64-float head row).
// Halves combine via shfl_xor(16). 40 LDG.128/warp vs 80 LDG.64 before.
__global__ void __launch_bounds__(512) sample_kernel(
        const float* __restrict__ offaw,
        const float* __restrict__ val,
        float* __restrict__ acc) {
    int w = threadIdx.y;
    int n = blockIdx.x * 4 + (w >> 2);
    int h = w & 3;
    int lane = threadIdx.x;

    float logit = (lane < 20) ? offaw[(size_t)n * NOA + 160 + h * 20 + lane] : -INFINITY;
    float mx = logit;
#pragma unroll
    for (int s = 16; s; s >>= 1) mx = fmaxf(mx, __shfl_xor_sync(0xFFFFFFFFu, mx, s));
    float e = (lane < 20) ? __expf(logit - mx) : 0.f;
    float sum = e;
#pragma unroll
    for (int s = 16; s; s >>= 1) sum += __shfl_xor_sync(0xFFFFFFFFu, sum, s);
    float w_sm = e / sum;

    float px = 0.f, py = 0.f;
    if (lane < 20) {
        int l = lane >> 2, p = lane & 3;
        int j = ((h * LL + l) * PP + p) * 2;
        float ox = offaw[(size_t)n * NOA + j];
        float oy = offaw[(size_t)n * NOA + j + 1];
        px = (float)(n & 127) + ox;
        py = (float)(n >> 7) + oy;
    }

    const int s16 = lane >> 4;        // half id: 0 or 1
    const int i4 = (lane & 15) * 4;   // float4 column offset within head
    float a[4] = {0.f, 0.f, 0.f, 0.f};
    for (int pp = 0; pp < 10; pp++) {
        int p = s16 * 10 + pp;
        float x  = __shfl_sync(0xFFFFFFFFu, px, p);
        float y  = __shfl_sync(0xFFFFFFFFu, py, p);
        float wp = __shfl_sync(0xFFFFFFFFu, w_sm, p);
        int l = p >> 2;
        float x0f = floorf(x), y0f = floorf(y);
        float fx = x - x0f, fy = y - y0f;
        int x0 = (int)x0f, y0 = (int)y0f;
        const float* base = val + (size_t)l * NQ * EE + h * HDD + i4;
#pragma unroll
        for (int dy = 0; dy < 2; dy++) {
#pragma unroll
            for (int dx = 0; dx < 2; dx++) {
                int ix = x0 + dx, iy = y0 + dy;
                bool valid = (ix >= 0) & (ix < 128) & (iy >= 0) & (iy < 128);
                float cw = ((dx ? fx : 1.f - fx) * (dy ? fy : 1.f - fy)) * wp;
                cw = valid ? cw : 0.f;
                int cx = min(max(ix, 0), 127);
                int cy = min(max(iy, 0), 127);
                int sidx = cy * 128 + cx;
                float4 gv = *(const float4*)(base + (size_t)sidx * EE);
                a[0] += cw * gv.x;
                a[1] += cw * gv.y;
                a[2] += cw * gv.z;
                a[3] += cw * gv.w;
            }
        }
    }
    // combine halves
#pragma unroll
    for (int k = 0; k < 4; k++) a[k] += __shfl_xor_sync(0xFFFFFFFFu, a[k], 16);
    if (s16 == 0) {
        int c0 = h * HDD + i4;
        size_t rowb = (size_t)n * EE;
        acc[rowb + permc(c0 + 0)] = f2tf(a[0]);
        acc[rowb + permc(c0 + 1)] = f2tf(a[1]);
        acc[rowb + permc(c0 + 2)] = f2tf(a[2]);
        acc[rowb + permc(c0 + 3)] = f2tf(a[3]);
    }
}

// ---------------- row LayerNorm over E=256 + rounded/permuted copies ----------------
__global__ void ln_kernel(float* __restrict__ x, const float* __restrict__ g,
                          const float* __restrict__ b,
                          float* __restrict__ rOut,
                          const float* __restrict__ prow, const float* __restrict__ pcol,
                          float* __restrict__ qpOut) {
    int row = blockIdx.x * 8 + threadIdx.y;
    int lane = threadIdx.x;
    float* xr = x + (size_t)row * 256 + lane * 8;
    float4 v0 = *(const float4*)xr;
    float4 v1 = *(const float4*)(xr + 4);
    float o[8] = {v0.x, v0.y, v0.z, v0.w, v1.x, v1.y, v1.z, v1.w};
    float s = 0.f, q2 = 0.f;
#pragma unroll
    for (int k = 0; k < 8; k++) { s += o[k]; q2 += o[k] * o[k]; }
#pragma unroll
    for (int sh = 16; sh; sh >>= 1) {
        s  += __shfl_xor_sync(0xFFFFFFFFu, s, sh);
        q2 += __shfl_xor_sync(0xFFFFFFFFu, q2, sh);
    }
    float mean = s * (1.f / 256.f);
    float var = q2 * (1.f / 256.f) - mean * mean;
    float rstd = rsqrtf(var + 1e-5f);
    int ecol = lane * 8;
#pragma unroll
    for (int k = 0; k < 8; k++) o[k] = (o[k] - mean) * rstd * g[ecol + k] + b[ecol + k];
    *(float4*)xr       = make_float4(o[0], o[1], o[2], o[3]);
    *(float4*)(xr + 4) = make_float4(o[4], o[5], o[6], o[7]);
    size_t base = (size_t)row * 256 + ecol;
    if (rOut) {
        *(float4*)(rOut + base)     = make_float4(f2tf(o[0]), f2tf(o[4]), f2tf(o[1]), f2tf(o[5]));
        *(float4*)(rOut + base + 4) = make_float4(f2tf(o[2]), f2tf(o[6]), f2tf(o[3]), f2tf(o[7]));
    }
    if (qpOut) {
        // pos computed on the fly (8-col group is entirely within one half)
        int ww = row & 127, hr = row >> 7;
        const float* psrc = (ecol < 128) ? (pcol + ww * 128 + ecol)
                                         : (prow + hr * 128 + (ecol - 128));
        float p[8];
        *(float4*)p       = *(const float4*)psrc;
        *(float4*)(p + 4) = *(const float4*)(psrc + 4);
        *(float4*)(qpOut + base)     = make_float4(f2tf(o[0] + p[0]), f2tf(o[4] + p[4]),
                                                   f2tf(o[1] + p[1]), f2tf(o[5] + p[5]));
        *(float4*)(qpOut + base + 4) = make_float4(f2tf(o[2] + p[2]), f2tf(o[6] + p[6]),
                                                   f2tf(o[3] + p[3]), f2tf(o[7] + p[7]));
    }
}

// ---------------- final transpose ----------------
__global__ void transpose_kernel(float* __restrict__ out) {
    __shared__ float t[32][33];
    int n0 = blockIdx.x * 32, e0 = blockIdx.y * 32;
    int tx = threadIdx.x, ty = threadIdx.y;
#pragma unroll
    for (int i = 0; i < 32; i += 8)
        t[ty + i][tx] = g_q[(size_t)(n0 + ty + i) * 256 + e0 + tx];
    __syncthreads();
#pragma unroll
    for (int i = 0; i < 32; i += 8)
        out[(size_t)(e0 + ty + i) * NQ + n0 + tx] = t[tx][ty + i];
}

// ---------------- host orchestration ----------------
extern "C" void kernel_launch(void* const* d_in, const int* in_sizes, int n_in,
                              void* d_out, int out_size) {
    const float* feat   = (const float*)d_in[0];
    const float* n0g    = (const float*)d_in[1];
    const float* n0b    = (const float*)d_in[2];
    const float* in_w   = (const float*)d_in[3];
    const float* in_b   = (const float*)d_in[4];
    const float* prow   = (const float*)d_in[5];
    const float* pcol   = (const float*)d_in[6];
    const float* off_w  = (const float*)d_in[7];
    const float* off_b  = (const float*)d_in[8];
    const float* aw_w   = (const float*)d_in[9];
    const float* aw_b   = (const float*)d_in[10];
    const float* val_w  = (const float*)d_in[11];
    const float* val_b  = (const float*)d_in[12];
    const float* out_w  = (const float*)d_in[13];
    const float* out_b  = (const float*)d_in[14];
    const float* ln1_g  = (const float*)d_in[15];
    const float* ln1_b  = (const float*)d_in[16];
    const float* ln2_g  = (const float*)d_in[17];
    const float* ln2_b  = (const float*)d_in[18];
    const float* ffn_w1 = (const float*)d_in[19];
    const float* ffn_b1 = (const float*)d_in[20];
    const float* ffn_w2 = (const float*)d_in[21];
    const float* ffn_b2 = (const float*)d_in[22];

    float *pf, *pq, *pqr, *pqp, *poa, *pval, *pacc, *ph;
    float *pwin, *pwoa, *pwval, *pwout, *pwf1, *pwf2, *pboa;
    cudaGetSymbolAddress((void**)&pf,    g_f);
    cudaGetSymbolAddress((void**)&pq,    g_q);
    cudaGetSymbolAddress((void**)&pqr,   g_qr);
    cudaGetSymbolAddress((void**)&pqp,   g_qp);
    cudaGetSymbolAddress((void**)&poa,   g_offaw);
    cudaGetSymbolAddress((void**)&pval,  g_val);
    cudaGetSymbolAddress((void**)&pacc,  g_acc);
    cudaGetSymbolAddress((void**)&ph,    g_h);
    cudaGetSymbolAddress((void**)&pwin,  g_w_in);
    cudaGetSymbolAddress((void**)&pwoa,  g_w_oa);
    cudaGetSymbolAddress((void**)&pwval, g_w_val);
    cudaGetSymbolAddress((void**)&pwout, g_w_out);
    cudaGetSymbolAddress((void**)&pwf1,  g_w_f1);
    cudaGetSymbolAddress((void**)&pwf2,  g_w_f2);
    cudaGetSymbolAddress((void**)&pboa,  g_b_oa);

    cudaFuncSetAttribute(gemm_ca<true, false, false, true>,
                         cudaFuncAttributeMaxDynamicSharedMemorySize, AKM_SMEM);
    cudaFuncSetAttribute(gemm_ca<true, false, false, false>,
                         cudaFuncAttributeMaxDynamicSharedMemorySize, AKM_SMEM);
    cudaFuncSetAttribute(gemm_ca<false, false, false, false>,
                         cudaFuncAttributeMaxDynamicSharedMemorySize, ROW_SMEM);
    cudaFuncSetAttribute(gemm_ca<false, true, true, false>,
                         cudaFuncAttributeMaxDynamicSharedMemorySize, ROW_SMEM);

    // ---- prologue: round weights (one batched launch), norm0 ----
    rcopy5_kernel<<<(NLAY * 256 * 512 + 255) / 256, 256>>>(
        in_w, pwin, 1280 * 256,
        val_w, pwval, NLAY * 256 * 256,
        out_w, pwout, NLAY * 256 * 256,
        ffn_w1, pwf1, NLAY * 256 * 512,
        ffn_w2, pwf2, NLAY * 512 * 256);
    pack_oa_kernel<<<(NLAY * EE * NOA + 255) / 256, 256>>>(off_w, off_b, aw_w, aw_b);
    norm0_kernel<<<dim3(NQ / 256, LL), 256>>>(feat, n0g, n0b);

    // input_proj: q = f^T @ in_w + in_b; aux qp = tf32(q + pos) with pos on the fly
    gemm_ca<true, false, false, true><<<dim3(2, 128), 256, AKM_SMEM>>>(
        pf, pwin, in_b, nullptr, pq, pqp, prow, pcol,
        NQ, 256, 1280, NQ, (size_t)CC * NQ, 0, 0);

    for (int i = 0; i < NLAY; i++) {
        // offsets + aw logits (N=240), A = qp (permuted tf32)
        gemm_ca<false, false, false, false><<<dim3(2, 128), 256, ROW_SMEM>>>(
            pqp, pwoa + (size_t)i * 256 * NOA, pboa + (size_t)i * NOA, nullptr,
            poa, nullptr, nullptr, nullptr, NQ, NOA, 256, 256, 0, 0, 0);
        // val projection, 5 levels via grid.z, A = g_f (K-major)
        gemm_ca<true, false, false, false><<<dim3(2, 128, LL), 256, AKM_SMEM>>>(
            pf, pwval + (size_t)i * 256 * 256, val_b + (size_t)i * EE, nullptr,
            pval, nullptr, nullptr, nullptr, NQ, 256, 256, NQ, 0,
            (size_t)CC * NQ, (size_t)NQ * EE);
        // sampling (half-warp point-split, float4 gathers)
        sample_kernel<<<NQ / 4, dim3(32, 16)>>>(poa, pval, pacc);
        // out proj + residual into q
        gemm_ca<false, false, false, false><<<dim3(2, 128), 256, ROW_SMEM>>>(
            pacc, pwout + (size_t)i * 256 * 256, out_b + (size_t)i * EE, pq,
            pq, nullptr, nullptr, nullptr, NQ, 256, 256, 256, 0, 0, 0);
        ln_kernel<<<NQ / 8, dim3(32, 8)>>>(pq, ln1_g + (size_t)i * EE, ln1_b + (size_t)i * EE,
                                           pqr, nullptr, nullptr, nullptr);
        // ffn1: relu, output h permuted tf32
        gemm_ca<false, true, true, false><<<dim3(4, 128), 256, ROW_SMEM>>>(
            pqr, pwf1 + (size_t)i * 256 * 512, ffn_b1 + (size_t)i * FFH, nullptr,
            ph, nullptr, nullptr, nullptr, NQ, 512, 256, 256, 0, 0, 0);
        // ffn2 + residual into q
        gemm_ca<false, false, false, false><<<dim3(2, 128), 256, ROW_SMEM>>>(
            ph, pwf2 + (size_t)i * 512 * 256, ffn_b2 + (size_t)i * EE, pq,
            pq, nullptr, nullptr, nullptr, NQ, 256, 512, 512, 0, 0, 0);
        // ln2: writes q fp32 + qp = tf32(q + pos) with pos on the fly
        ln_kernel<<<NQ / 8, dim3(32, 8)>>>(pq, ln2_g + (size_t)i * EE, ln2_b + (size_t)i * EE,
                                           nullptr, prow, pcol, pqp);
    }

    transpose_kernel<<<dim3(NQ / 32, EE / 32), dim3(32, 8)>>>((float*)d_out);
}

// round 15
// speedup vs baseline: 1.5518x; 1.3599x over previous
#include <cuda_runtime.h>
#include <cuda_fp16.h>
#include <math.h>
#include <stdint.h>

#define NQ 16384
#define CC 256
#define EE 256
#define LL 5
#define NHH 4
#define PP 4
#define HDD 64
#define FFH 512
#define NLAY 6
#define NOA 240

// ---------------- scratch (device globals; no allocation) ----------------
__device__ __half g_f[LL * CC * NQ];    // normed features as half2 [l][C/2][NQ]
__device__ float  g_q[NQ * EE];         // query fp32 [n][e]
__device__ __half g_qr[NQ * EE];        // half q (ffn1 A)
__device__ __half g_qp[NQ * EE];        // half q+pos (oa A)
__device__ float  g_offaw[NQ * NOA];    // fp32 [n][240]
__device__ float  g_val[LL * NQ * EE];  // fp32 [l][n][e]
__device__ __half g_acc[NQ * EE];       // half (out-proj A)
__device__ __half g_h[NQ * FFH];        // half (ffn2 A)
// half2-packed weights: [K/2][N]
__device__ __half2 g_w_in[640 * 256];
__device__ __half2 g_w_oa[NLAY * 128 * NOA + 64];  // pad for N-tile overrun
__device__ __half2 g_w_val[NLAY * 128 * 256];
__device__ __half2 g_w_out[NLAY * 128 * 256];
__device__ __half2 g_w_f1[NLAY * 128 * 512];
__device__ __half2 g_w_f2[NLAY * 256 * 256];
__device__ float g_b_oa[NLAY * NOA];

// ---------------- helpers ----------------
__device__ __forceinline__ uint32_t smem_u32(const void* p) {
    uint32_t a;
    asm("{ .reg .u64 t; cvta.to.shared.u64 t, %1; cvt.u32.u64 %0, t; }" : "=r"(a) : "l"(p));
    return a;
}
__device__ __forceinline__ void mma_f16(float* cc, const unsigned* a, const unsigned* b) {
    asm volatile(
        "mma.sync.aligned.m16n8k16.row.col.f32.f16.f16.f32 "
        "{%0,%1,%2,%3}, {%4,%5,%6,%7}, {%8,%9}, {%0,%1,%2,%3};\n"
        : "+f"(cc[0]), "+f"(cc[1]), "+f"(cc[2]), "+f"(cc[3])
        : "r"(a[0]), "r"(a[1]), "r"(a[2]), "r"(a[3]), "r"(b[0]), "r"(b[1]));
}
#define CPA16(sa, ga) asm volatile("cp.async.cg.shared.global [%0], [%1], 16;" :: "r"(sa), "l"(ga) : "memory")
#define CPA_COMMIT()  asm volatile("cp.async.commit_group;" ::: "memory")
#define CPA_WAIT(n)   asm volatile("cp.async.wait_group %0;" :: "n"(n) : "memory")

// ---------------- prologue kernels ----------------
// [K][N] fp32 -> [K/2][N] half2, batched over z
__global__ void wpack_kernel(const float* __restrict__ src, __half2* __restrict__ dst,
                             int K, int N, size_t sStride, size_t dStride) {
    src += blockIdx.z * sStride;
    dst += blockIdx.z * dStride;
    int idx = blockIdx.x * 256 + threadIdx.x;
    if (idx >= (K >> 1) * N) return;
    int k2 = idx / N, n = idx % N;
    dst[idx] = __floats2half2_rn(src[(size_t)(2 * k2) * N + n],
                                 src[(size_t)(2 * k2 + 1) * N + n]);
}

// pack off|aw -> [K/2=128][N=240] half2 per layer
__global__ void pack_oa_kernel(const float* __restrict__ off_w, const float* __restrict__ off_b,
                               const float* __restrict__ aw_w, const float* __restrict__ aw_b) {
    int idx = blockIdx.x * 256 + threadIdx.x;
    if (idx >= NLAY * 128 * NOA) return;
    int c = idx % NOA;
    int e2 = (idx / NOA) % 128;
    int i = idx / (NOA * 128);
    int e0 = 2 * e2, e1 = 2 * e2 + 1;
    float v0 = (c < 160) ? off_w[((size_t)i * EE + e0) * 160 + c]
                         : aw_w[((size_t)i * EE + e0) * 80 + (c - 160)];
    float v1 = (c < 160) ? off_w[((size_t)i * EE + e1) * 160 + c]
                         : aw_w[((size_t)i * EE + e1) * 80 + (c - 160)];
    g_w_oa[idx] = __floats2half2_rn(v0, v1);
    if (e2 == 0)
        g_b_oa[i * NOA + c] = (c < 160) ? off_b[i * 160 + c] : aw_b[i * 80 + (c - 160)];
}

// per-(l,n) LN over channels, writes half2 [l][c2][NQ]
__global__ void norm0_kernel(const float* __restrict__ feat,
                             const float* __restrict__ g,
                             const float* __restrict__ b) {
    int n = blockIdx.x * blockDim.x + threadIdx.x;
    int l = blockIdx.y;
    const float* src = feat + (size_t)l * CC * NQ + n;
    float sum = 0.f, sq = 0.f;
#pragma unroll 8
    for (int c = 0; c < CC; c++) {
        float v = src[(size_t)c * NQ];
        sum += v; sq += v * v;
    }
    float mean = sum * (1.f / CC);
    float var = sq * (1.f / CC) - mean * mean;
    float rstd = rsqrtf(var + 1e-5f);
    __half2* dst = (__half2*)g_f + (size_t)l * 128 * NQ + n;
#pragma unroll 4
    for (int c2 = 0; c2 < 128; c2++) {
        int c = 2 * c2;
        float v0 = (src[(size_t)c * NQ] - mean) * rstd * g[l * CC + c] + b[l * CC + c];
        float v1 = (src[(size_t)(c + 1) * NQ] - mean) * rstd * g[l * CC + c + 1] + b[l * CC + c + 1];
        dst[(size_t)c2 * NQ] = __floats2half2_rn(v0, v1);
    }
}

// ---------------- fp16 tensor-core GEMM, cp.async 4-stage, K=32/stage ----------------
#define ROWH 40                      // halves per A row in row-path smem (80B)
#define PADB 136                     // half2 per row for AKM-A and B smem
#define STAGES 4
#define RA_BYTES (128 * ROWH * 2)    // 10240
#define KB_BYTES (16 * PADB * 4)     // 8704
#define ROW_SMEM (STAGES * (RA_BYTES + KB_BYTES))
#define AKM_SMEM (STAGES * (KB_BYTES + KB_BYTES))

template <bool AKM, bool RELU, bool HOUT, bool AUXQP>
__global__ void __launch_bounds__(256, 2) gemm_h(
    const __half* __restrict__ Ah,        // row path: [M][ldaH] half
    const __half2* __restrict__ A2,       // AKM path: [K/2][lda2] half2
    const __half2* __restrict__ B2,       // [K/2][N] half2
    const float* __restrict__ bias, const float* __restrict__ resid,
    float* __restrict__ Cf, __half* __restrict__ Ch, __half* __restrict__ Caux,
    const float* __restrict__ Prow, const float* __restrict__ Pcol,
    int N, int K, int ldaH, int lda2,
    int blkShift2, size_t aBlockStride2, size_t aZ2, size_t cZ) {
    extern __shared__ __align__(16) char sraw[];
    constexpr int ASZ = AKM ? KB_BYTES : RA_BYTES;
    constexpr int BSZ = KB_BYTES;
    char* AsBase = sraw;
    char* BsBase = sraw + STAGES * ASZ;

    const int tid = threadIdx.x;
    const int warp = tid >> 5, lane = tid & 31;
    const int m0 = blockIdx.y * 128, n0 = blockIdx.x * 128;
    if (AKM) A2 += blockIdx.z * aZ2;
    Cf += blockIdx.z * cZ;
    const int wm = (warp & 3) * 32, wn = (warp >> 2) * 64;
    const int r = lane >> 2, cq = lane & 3;

    const uint32_t uA = smem_u32(AsBase);
    const uint32_t uB = smem_u32(BsBase);
    const int KT = K >> 5;   // 32 halves per stage

    float acc[2][8][4];
#pragma unroll
    for (int mt = 0; mt < 2; mt++)
#pragma unroll
        for (int nt = 0; nt < 8; nt++)
#pragma unroll
            for (int k = 0; k < 4; k++) acc[mt][nt][k] = 0.f;

    auto ld_stage = [&](int kt) {
        int st = kt & (STAGES - 1);
        int kk2 = kt << 4;               // half2 row base
        if (AKM) {
            int blk = kk2 >> blkShift2;
            int kin2 = kk2 - (blk << blkShift2);
            const __half2* base = A2 + (size_t)blk * aBlockStride2;
#pragma unroll
            for (int t = 0; t < 2; t++) {
                int ch = tid + t * 256;
                int j = ch >> 5, co = (ch & 31) << 2;
                CPA16(uA + (uint32_t)(st * ASZ) + (uint32_t)(j * PADB + co) * 4,
                      base + (size_t)(kin2 + j) * lda2 + m0 + co);
            }
        } else {
            int kkh = kt << 5;
#pragma unroll
            for (int t = 0; t < 2; t++) {
                int ch = tid + t * 256;
                int i = ch >> 2, kc = (ch & 3) << 3;   // halves
                CPA16(uA + (uint32_t)(st * ASZ) + (uint32_t)(i * ROWH + kc) * 2,
                      Ah + (size_t)(m0 + i) * ldaH + kkh + kc);
            }
        }
#pragma unroll
        for (int t = 0; t < 2; t++) {
            int ch = tid + t * 256;
            int j = ch >> 5, co = (ch & 31) << 2;
            CPA16(uB + (uint32_t)(st * BSZ) + (uint32_t)(j * PADB + co) * 4,
                  B2 + (size_t)(kk2 + j) * N + n0 + co);
        }
    };

#pragma unroll
    for (int s = 0; s < STAGES - 1; s++) { ld_stage(s); CPA_COMMIT(); }

    for (int kt = 0; kt < KT; kt++) {
        CPA_WAIT(STAGES - 2);
        __syncthreads();
        if (kt + STAGES - 1 < KT) ld_stage(kt + STAGES - 1);
        CPA_COMMIT();

        const int st = kt & (STAGES - 1);
        const uint32_t* a_s = (const uint32_t*)(AsBase + st * ASZ);
        const uint32_t* b_s = (const uint32_t*)(BsBase + st * BSZ);
#pragma unroll
        for (int g = 0; g < 2; g++) {     // two k16 groups per stage
            unsigned af[2][4], bf[8][2];
#pragma unroll
            for (int mt = 0; mt < 2; mt++) {
                int mb = wm + mt * 16 + r;
                if (AKM) {
                    af[mt][0] = a_s[(g * 8 + cq) * PADB + mb];
                    af[mt][1] = a_s[(g * 8 + cq) * PADB + mb + 8];
                    af[mt][2] = a_s[(g * 8 + 4 + cq) * PADB + mb];
                    af[mt][3] = a_s[(g * 8 + 4 + cq) * PADB + mb + 8];
                } else {
                    int bi = mb * 20 + g * 8 + cq;   // uint units (ROWH/2=20)
                    af[mt][0] = a_s[bi];
                    af[mt][1] = a_s[bi + 160];       // m+8 rows
                    af[mt][2] = a_s[bi + 4];         // k+8 halves
                    af[mt][3] = a_s[bi + 164];
                }
            }
#pragma unroll
            for (int nt = 0; nt < 8; nt++) {
                int nb = wn + nt * 8 + r;
                bf[nt][0] = b_s[(g * 8 + cq) * PADB + nb];
                bf[nt][1] = b_s[(g * 8 + 4 + cq) * PADB + nb];
            }
#pragma unroll
            for (int mt = 0; mt < 2; mt++)
#pragma unroll
                for (int nt = 0; nt < 8; nt++)
                    mma_f16(acc[mt][nt], af[mt], bf[nt]);
        }
    }

    // ---- epilogue ----
#pragma unroll
    for (int mt = 0; mt < 2; mt++) {
#pragma unroll
        for (int nt = 0; nt < 8; nt++) {
            int row = m0 + wm + mt * 16 + r;
            int col = n0 + wn + nt * 8 + 2 * cq;
            if (col < N) {
                float b0 = bias[col], b1 = bias[col + 1];
#pragma unroll
                for (int hh = 0; hh < 2; hh++) {
                    int rr = row + hh * 8;
                    float v0 = acc[mt][nt][hh * 2 + 0] + b0;
                    float v1 = acc[mt][nt][hh * 2 + 1] + b1;
                    if (resid) {
                        float2 rv = *(const float2*)(resid + (size_t)rr * N + col);
                        v0 += rv.x; v1 += rv.y;
                    }
                    if (RELU) { v0 = fmaxf(v0, 0.f); v1 = fmaxf(v1, 0.f); }
                    if (HOUT) {
                        *(__half2*)(Ch + (size_t)rr * N + col) = __floats2half2_rn(v0, v1);
                    } else {
                        *(float2*)(Cf + (size_t)rr * N + col) = make_float2(v0, v1);
                        if (AUXQP) {
                            int ww = rr & 127, hr = rr >> 7;
                            float p0, p1;
                            if (col < 128) {
                                p0 = Pcol[ww * 128 + col];
                                p1 = Pcol[ww * 128 + col + 1];
                            } else {
                                p0 = Prow[hr * 128 + col - 128];
                                p1 = Prow[hr * 128 + col - 127];
                            }
                            *(__half2*)(Caux + (size_t)rr * 256 + col) =
                                __floats2half2_rn(v0 + p0, v1 + p1);
                        }
                    }
                }
            }
        }
    }
}

// ---------------- fused softmax + bilinear deformable sampling ----------------
// grid NQ/4, block (32,16): warp=(query,head); half-warp point-split, float4 gathers.
__global__ void __launch_bounds__(512) sample_kernel(
        const float* __restrict__ offaw,
        const float* __restrict__ val,
        __half* __restrict__ acc) {
    int w = threadIdx.y;
    int n = blockIdx.x * 4 + (w >> 2);
    int h = w & 3;
    int lane = threadIdx.x;

    float logit = (lane < 20) ? offaw[(size_t)n * NOA + 160 + h * 20 + lane] : -INFINITY;
    float mx = logit;
#pragma unroll
    for (int s = 16; s; s >>= 1) mx = fmaxf(mx, __shfl_xor_sync(0xFFFFFFFFu, mx, s));
    float e = (lane < 20) ? __expf(logit - mx) : 0.f;
    float sum = e;
#pragma unroll
    for (int s = 16; s; s >>= 1) sum += __shfl_xor_sync(0xFFFFFFFFu, sum, s);
    float w_sm = e / sum;

    float px = 0.f, py = 0.f;
    if (lane < 20) {
        int l = lane >> 2, p = lane & 3;
        int j = ((h * LL + l) * PP + p) * 2;
        float ox = offaw[(size_t)n * NOA + j];
        float oy = offaw[(size_t)n * NOA + j + 1];
        px = (float)(n & 127) + ox;
        py = (float)(n >> 7) + oy;
    }

    const int s16 = lane >> 4;
    const int i4 = (lane & 15) * 4;
    float a[4] = {0.f, 0.f, 0.f, 0.f};
    for (int pp = 0; pp < 10; pp++) {
        int p = s16 * 10 + pp;
        float x  = __shfl_sync(0xFFFFFFFFu, px, p);
        float y  = __shfl_sync(0xFFFFFFFFu, py, p);
        float wp = __shfl_sync(0xFFFFFFFFu, w_sm, p);
        int l = p >> 2;
        float x0f = floorf(x), y0f = floorf(y);
        float fx = x - x0f, fy = y - y0f;
        int x0 = (int)x0f, y0 = (int)y0f;
        const float* base = val + (size_t)l * NQ * EE + h * HDD + i4;
#pragma unroll
        for (int dy = 0; dy < 2; dy++) {
#pragma unroll
            for (int dx = 0; dx < 2; dx++) {
                int ix = x0 + dx, iy = y0 + dy;
                bool valid = (ix >= 0) & (ix < 128) & (iy >= 0) & (iy < 128);
                float cw = ((dx ? fx : 1.f - fx) * (dy ? fy : 1.f - fy)) * wp;
                cw = valid ? cw : 0.f;
                int cx = min(max(ix, 0), 127);
                int cy = min(max(iy, 0), 127);
                int sidx = cy * 128 + cx;
                float4 gv = *(const float4*)(base + (size_t)sidx * EE);
                a[0] += cw * gv.x;
                a[1] += cw * gv.y;
                a[2] += cw * gv.z;
                a[3] += cw * gv.w;
            }
        }
    }
#pragma unroll
    for (int k = 0; k < 4; k++) a[k] += __shfl_xor_sync(0xFFFFFFFFu, a[k], 16);
    if (s16 == 0) {
        int c0 = h * HDD + i4;
        __half2 h01 = __floats2half2_rn(a[0], a[1]);
        __half2 h23 = __floats2half2_rn(a[2], a[3]);
        *(uint2*)(acc + (size_t)n * EE + c0) =
            make_uint2(*(unsigned*)&h01, *(unsigned*)&h23);
    }
}

// ---------------- row LayerNorm over E=256 + half copies ----------------
__global__ void ln_kernel(float* __restrict__ x, const float* __restrict__ g,
                          const float* __restrict__ b,
                          __half* __restrict__ rOut,
                          const float* __restrict__ prow, const float* __restrict__ pcol,
                          __half* __restrict__ qpOut) {
    int row = blockIdx.x * 8 + threadIdx.y;
    int lane = threadIdx.x;
    float* xr = x + (size_t)row * 256 + lane * 8;
    float4 v0 = *(const float4*)xr;
    float4 v1 = *(const float4*)(xr + 4);
    float o[8] = {v0.x, v0.y, v0.z, v0.w, v1.x, v1.y, v1.z, v1.w};
    float s = 0.f, q2 = 0.f;
#pragma unroll
    for (int k = 0; k < 8; k++) { s += o[k]; q2 += o[k] * o[k]; }
#pragma unroll
    for (int sh = 16; sh; sh >>= 1) {
        s  += __shfl_xor_sync(0xFFFFFFFFu, s, sh);
        q2 += __shfl_xor_sync(0xFFFFFFFFu, q2, sh);
    }
    float mean = s * (1.f / 256.f);
    float var = q2 * (1.f / 256.f) - mean * mean;
    float rstd = rsqrtf(var + 1e-5f);
    int ecol = lane * 8;
#pragma unroll
    for (int k = 0; k < 8; k++) o[k] = (o[k] - mean) * rstd * g[ecol + k] + b[ecol + k];
    *(float4*)xr       = make_float4(o[0], o[1], o[2], o[3]);
    *(float4*)(xr + 4) = make_float4(o[4], o[5], o[6], o[7]);
    size_t base = (size_t)row * 256 + ecol;
    if (rOut) {
        __half2 p0 = __floats2half2_rn(o[0], o[1]);
        __half2 p1 = __floats2half2_rn(o[2], o[3]);
        __half2 p2 = __floats2half2_rn(o[4], o[5]);
        __half2 p3 = __floats2half2_rn(o[6], o[7]);
        *(uint4*)(rOut + base) = make_uint4(*(unsigned*)&p0, *(unsigned*)&p1,
                                            *(unsigned*)&p2, *(unsigned*)&p3);
    }
    if (qpOut) {
        int ww = row & 127, hr = row >> 7;
        const float* psrc = (ecol < 128) ? (pcol + ww * 128 + ecol)
                                         : (prow + hr * 128 + (ecol - 128));
        float p[8];
        *(float4*)p       = *(const float4*)psrc;
        *(float4*)(p + 4) = *(const float4*)(psrc + 4);
        __half2 q0 = __floats2half2_rn(o[0] + p[0], o[1] + p[1]);
        __half2 q1 = __floats2half2_rn(o[2] + p[2], o[3] + p[3]);
        __half2 q2h = __floats2half2_rn(o[4] + p[4], o[5] + p[5]);
        __half2 q3 = __floats2half2_rn(o[6] + p[6], o[7] + p[7]);
        *(uint4*)(qpOut + base) = make_uint4(*(unsigned*)&q0, *(unsigned*)&q1,
                                             *(unsigned*)&q2h, *(unsigned*)&q3);
    }
}

// ---------------- final transpose ----------------
__global__ void transpose_kernel(float* __restrict__ out) {
    __shared__ float t[32][33];
    int n0 = blockIdx.x * 32, e0 = blockIdx.y * 32;
    int tx = threadIdx.x, ty = threadIdx.y;
#pragma unroll
    for (int i = 0; i < 32; i += 8)
        t[ty + i][tx] = g_q[(size_t)(n0 + ty + i) * 256 + e0 + tx];
    __syncthreads();
#pragma unroll
    for (int i = 0; i < 32; i += 8)
        out[(size_t)(e0 + ty + i) * NQ + n0 + tx] = t[tx][ty + i];
}

// ---------------- host orchestration ----------------
extern "C" void kernel_launch(void* const* d_in, const int* in_sizes, int n_in,
                              void* d_out, int out_size) {
    const float* feat   = (const float*)d_in[0];
    const float* n0g    = (const float*)d_in[1];
    const float* n0b    = (const float*)d_in[2];
    const float* in_w   = (const float*)d_in[3];
    const float* in_b   = (const float*)d_in[4];
    const float* prow   = (const float*)d_in[5];
    const float* pcol   = (const float*)d_in[6];
    const float* off_w  = (const float*)d_in[7];
    const float* off_b  = (const float*)d_in[8];
    const float* aw_w   = (const float*)d_in[9];
    const float* aw_b   = (const float*)d_in[10];
    const float* val_w  = (const float*)d_in[11];
    const float* val_b  = (const float*)d_in[12];
    const float* out_w  = (const float*)d_in[13];
    const float* out_b  = (const float*)d_in[14];
    const float* ln1_g  = (const float*)d_in[15];
    const float* ln1_b  = (const float*)d_in[16];
    const float* ln2_g  = (const float*)d_in[17];
    const float* ln2_b  = (const float*)d_in[18];
    const float* ffn_w1 = (const float*)d_in[19];
    const float* ffn_b1 = (const float*)d_in[20];
    const float* ffn_w2 = (const float*)d_in[21];
    const float* ffn_b2 = (const float*)d_in[22];

    __half *pf, *pqr, *pqp, *pacc, *ph;
    float *pq, *poa, *pval, *pboa;
    __half2 *pwin, *pwoa, *pwval, *pwout, *pwf1, *pwf2;
    cudaGetSymbolAddress((void**)&pf,    g_f);
    cudaGetSymbolAddress((void**)&pq,    g_q);
    cudaGetSymbolAddress((void**)&pqr,   g_qr);
    cudaGetSymbolAddress((void**)&pqp,   g_qp);
    cudaGetSymbolAddress((void**)&poa,   g_offaw);
    cudaGetSymbolAddress((void**)&pval,  g_val);
    cudaGetSymbolAddress((void**)&pacc,  g_acc);
    cudaGetSymbolAddress((void**)&ph,    g_h);
    cudaGetSymbolAddress((void**)&pwin,  g_w_in);
    cudaGetSymbolAddress((void**)&pwoa,  g_w_oa);
    cudaGetSymbolAddress((void**)&pwval, g_w_val);
    cudaGetSymbolAddress((void**)&pwout, g_w_out);
    cudaGetSymbolAddress((void**)&pwf1,  g_w_f1);
    cudaGetSymbolAddress((void**)&pwf2,  g_w_f2);
    cudaGetSymbolAddress((void**)&pboa,  g_b_oa);

    cudaFuncSetAttribute(gemm_h<true, false, false, true>,
                         cudaFuncAttributeMaxDynamicSharedMemorySize, AKM_SMEM);
    cudaFuncSetAttribute(gemm_h<true, false, false, false>,
                         cudaFuncAttributeMaxDynamicSharedMemorySize, AKM_SMEM);
    cudaFuncSetAttribute(gemm_h<false, false, false, false>,
                         cudaFuncAttributeMaxDynamicSharedMemorySize, ROW_SMEM);
    cudaFuncSetAttribute(gemm_h<false, true, true, false>,
                         cudaFuncAttributeMaxDynamicSharedMemorySize, ROW_SMEM);

    // ---- prologue: pack weights to half2, norm0 ----
    wpack_kernel<<<dim3((640 * 256 + 255) / 256, 1, 1), 256>>>(in_w, pwin, 1280, 256, 0, 0);
    wpack_kernel<<<dim3((128 * 256 + 255) / 256, 1, NLAY), 256>>>(
        val_w, pwval, 256, 256, (size_t)256 * 256, (size_t)128 * 256);
    wpack_kernel<<<dim3((128 * 256 + 255) / 256, 1, NLAY), 256>>>(
        out_w, pwout, 256, 256, (size_t)256 * 256, (size_t)128 * 256);
    wpack_kernel<<<dim3((128 * 512 + 255) / 256, 1, NLAY), 256>>>(
        ffn_w1, pwf1, 256, 512, (size_t)256 * 512, (size_t)128 * 512);
    wpack_kernel<<<dim3((256 * 256 + 255) / 256, 1, NLAY), 256>>>(
        ffn_w2, pwf2, 512, 256, (size_t)512 * 256, (size_t)256 * 256);
    pack_oa_kernel<<<(NLAY * 128 * NOA + 255) / 256, 256>>>(off_w, off_b, aw_w, aw_b);
    norm0_kernel<<<dim3(NQ / 256, LL), 256>>>(feat, n0g, n0b);

    // input_proj (AKM, K=1280, level hop every 128 half2 rows); aux qp half
    gemm_h<true, false, false, true><<<dim3(2, 128), 256, AKM_SMEM>>>(
        nullptr, (const __half2*)pf, pwin, in_b, nullptr, pq, nullptr, pqp, prow, pcol,
        256, 1280, 0, NQ, 7, (size_t)128 * NQ, 0, 0);

    for (int i = 0; i < NLAY; i++) {
        // offsets + aw logits (N=240), A = qp half row-major
        gemm_h<false, false, false, false><<<dim3(2, 128), 256, ROW_SMEM>>>(
            pqp, nullptr, pwoa + (size_t)i * 128 * NOA, pboa + (size_t)i * NOA, nullptr,
            poa, nullptr, nullptr, nullptr, nullptr,
            NOA, 256, 256, 0, 30, 0, 0, 0);
        // val projection, 5 levels via grid.z (AKM)
        gemm_h<true, false, false, false><<<dim3(2, 128, LL), 256, AKM_SMEM>>>(
            nullptr, (const __half2*)pf, pwval + (size_t)i * 128 * 256,
            val_b + (size_t)i * EE, nullptr, pval, nullptr, nullptr, nullptr, nullptr,
            256, 256, 0, NQ, 30, 0, (size_t)128 * NQ, (size_t)NQ * EE);
        // sampling -> half acc
        sample_kernel<<<NQ / 4, dim3(32, 16)>>>(poa, pval, pacc);
        // out proj + residual into q (fp32)
        gemm_h<false, false, false, false><<<dim3(2, 128), 256, ROW_SMEM>>>(
            pacc, nullptr, pwout + (size_t)i * 128 * 256, out_b + (size_t)i * EE, pq,
            pq, nullptr, nullptr, nullptr, nullptr,
            256, 256, 256, 0, 30, 0, 0, 0);
        ln_kernel<<<NQ / 8, dim3(32, 8)>>>(pq, ln1_g + (size_t)i * EE, ln1_b + (size_t)i * EE,
                                           pqr, nullptr, nullptr, nullptr);
        // ffn1: relu, half output h
        gemm_h<false, true, true, false><<<dim3(4, 128), 256, ROW_SMEM>>>(
            pqr, nullptr, pwf1 + (size_t)i * 128 * 512, ffn_b1 + (size_t)i * FFH, nullptr,
            nullptr, ph, nullptr, nullptr, nullptr,
            512, 256, 256, 0, 30, 0, 0, 0);
        // ffn2 + residual into q
        gemm_h<false, false, false, false><<<dim3(2, 128), 256, ROW_SMEM>>>(
            ph, nullptr, pwf2 + (size_t)i * 256 * 256, ffn_b2 + (size_t)i * EE, pq,
            pq, nullptr, nullptr, nullptr, nullptr,
            256, 512, 512, 0, 30, 0, 0, 0);
        // ln2: q fp32 + qp = half(q + pos)
        ln_kernel<<<NQ / 8, dim3(32, 8)>>>(pq, ln2_g + (size_t)i * EE, ln2_b + (size_t)i * EE,
                                           nullptr, prow, pcol, pqp);
    }

    transpose_kernel<<<dim3(NQ / 32, EE / 32), dim3(32, 8)>>>((float*)d_out);
}

// round 17
// speedup vs baseline: 1.6510x; 1.0639x over previous
#include <cuda_runtime.h>
#include <cuda_fp16.h>
#include <math.h>
#include <stdint.h>

#define NQ 16384
#define CC 256
#define EE 256
#define LL 5
#define NHH 4
#define PP 4
#define HDD 64
#define FFH 512
#define NLAY 6
#define NOA 240

// ---------------- scratch (device globals; no allocation) ----------------
__device__ __half g_f[LL * CC * NQ];    // normed features as half2 [l][C/2][NQ]
__device__ float  g_q[NQ * EE];         // query fp32 [n][e]
__device__ __half g_qr[NQ * EE];        // half q (ffn1 A)
__device__ __half g_qp[NQ * EE];        // half q+pos (oa A)
__device__ float  g_offaw[NQ * NOA];    // fp32 [n][240]
__device__ __half g_val[LL * NQ * EE];  // half [l][n][e]
__device__ __half g_acc[NQ * EE];       // half (out-proj A)
__device__ __half g_h[NQ * FFH];        // half (ffn2 A)
// half2-packed weights: [K/2][N]
__device__ __half2 g_w_in[640 * 256];
__device__ __half2 g_w_oa[NLAY * 128 * NOA + 64];  // pad for N-tile overrun
__device__ __half2 g_w_val[NLAY * 128 * 256];
__device__ __half2 g_w_out[NLAY * 128 * 256];
__device__ __half2 g_w_f1[NLAY * 128 * 512];
__device__ __half2 g_w_f2[NLAY * 256 * 256];
__device__ float g_b_oa[NLAY * NOA];

// ---------------- helpers ----------------
__device__ __forceinline__ uint32_t smem_u32(const void* p) {
    uint32_t a;
    asm("{ .reg .u64 t; cvta.to.shared.u64 t, %1; cvt.u32.u64 %0, t; }" : "=r"(a) : "l"(p));
    return a;
}
__device__ __forceinline__ void mma_f16(float* cc, const unsigned* a, const unsigned* b) {
    asm volatile(
        "mma.sync.aligned.m16n8k16.row.col.f32.f16.f16.f32 "
        "{%0,%1,%2,%3}, {%4,%5,%6,%7}, {%8,%9}, {%0,%1,%2,%3};\n"
        : "+f"(cc[0]), "+f"(cc[1]), "+f"(cc[2]), "+f"(cc[3])
        : "r"(a[0]), "r"(a[1]), "r"(a[2]), "r"(a[3]), "r"(b[0]), "r"(b[1]));
}
#define CPA16(sa, ga) asm volatile("cp.async.cg.shared.global [%0], [%1], 16;" :: "r"(sa), "l"(ga) : "memory")
#define CPA_COMMIT()  asm volatile("cp.async.commit_group;" ::: "memory")
#define CPA_WAIT(n)   asm volatile("cp.async.wait_group %0;" :: "n"(n) : "memory")

// ---------------- prologue kernels ----------------
// [K][N] fp32 -> [K/2][N] half2, batched over z
__global__ void wpack_kernel(const float* __restrict__ src, __half2* __restrict__ dst,
                             int K, int N, size_t sStride, size_t dStride) {
    src += blockIdx.z * sStride;
    dst += blockIdx.z * dStride;
    int idx = blockIdx.x * 256 + threadIdx.x;
    if (idx >= (K >> 1) * N) return;
    int k2 = idx / N, n = idx % N;
    dst[idx] = __floats2half2_rn(src[(size_t)(2 * k2) * N + n],
                                 src[(size_t)(2 * k2 + 1) * N + n]);
}

// pack off|aw -> [K/2=128][N=240] half2 per layer
__global__ void pack_oa_kernel(const float* __restrict__ off_w, const float* __restrict__ off_b,
                               const float* __restrict__ aw_w, const float* __restrict__ aw_b) {
    int idx = blockIdx.x * 256 + threadIdx.x;
    if (idx >= NLAY * 128 * NOA) return;
    int c = idx % NOA;
    int e2 = (idx / NOA) % 128;
    int i = idx / (NOA * 128);
    int e0 = 2 * e2, e1 = 2 * e2 + 1;
    float v0 = (c < 160) ? off_w[((size_t)i * EE + e0) * 160 + c]
                         : aw_w[((size_t)i * EE + e0) * 80 + (c - 160)];
    float v1 = (c < 160) ? off_w[((size_t)i * EE + e1) * 160 + c]
                         : aw_w[((size_t)i * EE + e1) * 80 + (c - 160)];
    g_w_oa[idx] = __floats2half2_rn(v0, v1);
    if (e2 == 0)
        g_b_oa[i * NOA + c] = (c < 160) ? off_b[i * 160 + c] : aw_b[i * 80 + (c - 160)];
}

// per-(l,n) LN over channels, writes half2 [l][c2][NQ]
__global__ void norm0_kernel(const float* __restrict__ feat,
                             const float* __restrict__ g,
                             const float* __restrict__ b) {
    int n = blockIdx.x * blockDim.x + threadIdx.x;
    int l = blockIdx.y;
    const float* src = feat + (size_t)l * CC * NQ + n;
    float sum = 0.f, sq = 0.f;
#pragma unroll 8
    for (int c = 0; c < CC; c++) {
        float v = src[(size_t)c * NQ];
        sum += v; sq += v * v;
    }
    float mean = sum * (1.f / CC);
    float var = sq * (1.f / CC) - mean * mean;
    float rstd = rsqrtf(var + 1e-5f);
    __half2* dst = (__half2*)g_f + (size_t)l * 128 * NQ + n;
#pragma unroll 4
    for (int c2 = 0; c2 < 128; c2++) {
        int c = 2 * c2;
        float v0 = (src[(size_t)c * NQ] - mean) * rstd * g[l * CC + c] + b[l * CC + c];
        float v1 = (src[(size_t)(c + 1) * NQ] - mean) * rstd * g[l * CC + c + 1] + b[l * CC + c + 1];
        dst[(size_t)c2 * NQ] = __floats2half2_rn(v0, v1);
    }
}

// ---------------- fp16 tensor-core GEMM, cp.async 4-stage, K=32/stage ----------------
#define ROWH 40                      // halves per A row in row-path smem (80B)
#define PADB 136                     // half2 per row for AKM-A and B smem
#define STAGES 4
#define RA_BYTES (128 * ROWH * 2)    // 10240
#define KB_BYTES (16 * PADB * 4)     // 8704
#define ROW_SMEM (STAGES * (RA_BYTES + KB_BYTES))
#define AKM_SMEM (STAGES * (KB_BYTES + KB_BYTES))

template <bool AKM, bool RELU, bool HOUT, bool AUXQP>
__global__ void __launch_bounds__(256, 2) gemm_h(
    const __half* __restrict__ Ah,        // row path: [M][ldaH] half
    const __half2* __restrict__ A2,       // AKM path: [K/2][lda2] half2
    const __half2* __restrict__ B2,       // [K/2][N] half2
    const float* __restrict__ bias, const float* __restrict__ resid,
    float* __restrict__ Cf, __half* __restrict__ Ch, __half* __restrict__ Caux,
    const float* __restrict__ Prow, const float* __restrict__ Pcol,
    int N, int K, int ldaH, int lda2,
    int blkShift2, size_t aBlockStride2, size_t aZ2, size_t cZ) {
    extern __shared__ __align__(16) char sraw[];
    constexpr int ASZ = AKM ? KB_BYTES : RA_BYTES;
    constexpr int BSZ = KB_BYTES;
    char* AsBase = sraw;
    char* BsBase = sraw + STAGES * ASZ;

    const int tid = threadIdx.x;
    const int warp = tid >> 5, lane = tid & 31;
    const int m0 = blockIdx.y * 128, n0 = blockIdx.x * 128;
    if (AKM) A2 += blockIdx.z * aZ2;
    if (HOUT) Ch += blockIdx.z * cZ; else Cf += blockIdx.z * cZ;
    const int wm = (warp & 3) * 32, wn = (warp >> 2) * 64;
    const int r = lane >> 2, cq = lane & 3;

    const uint32_t uA = smem_u32(AsBase);
    const uint32_t uB = smem_u32(BsBase);
    const int KT = K >> 5;   // 32 halves per stage

    float acc[2][8][4];
#pragma unroll
    for (int mt = 0; mt < 2; mt++)
#pragma unroll
        for (int nt = 0; nt < 8; nt++)
#pragma unroll
            for (int k = 0; k < 4; k++) acc[mt][nt][k] = 0.f;

    auto ld_stage = [&](int kt) {
        int st = kt & (STAGES - 1);
        int kk2 = kt << 4;               // half2 row base
        if (AKM) {
            int blk = kk2 >> blkShift2;
            int kin2 = kk2 - (blk << blkShift2);
            const __half2* base = A2 + (size_t)blk * aBlockStride2;
#pragma unroll
            for (int t = 0; t < 2; t++) {
                int ch = tid + t * 256;
                int j = ch >> 5, co = (ch & 31) << 2;
                CPA16(uA + (uint32_t)(st * ASZ) + (uint32_t)(j * PADB + co) * 4,
                      base + (size_t)(kin2 + j) * lda2 + m0 + co);
            }
        } else {
            int kkh = kt << 5;
#pragma unroll
            for (int t = 0; t < 2; t++) {
                int ch = tid + t * 256;
                int i = ch >> 2, kc = (ch & 3) << 3;   // halves
                CPA16(uA + (uint32_t)(st * ASZ) + (uint32_t)(i * ROWH + kc) * 2,
                      Ah + (size_t)(m0 + i) * ldaH + kkh + kc);
            }
        }
#pragma unroll
        for (int t = 0; t < 2; t++) {
            int ch = tid + t * 256;
            int j = ch >> 5, co = (ch & 31) << 2;
            CPA16(uB + (uint32_t)(st * BSZ) + (uint32_t)(j * PADB + co) * 4,
                  B2 + (size_t)(kk2 + j) * N + n0 + co);
        }
    };

#pragma unroll
    for (int s = 0; s < STAGES - 1; s++) { ld_stage(s); CPA_COMMIT(); }

    for (int kt = 0; kt < KT; kt++) {
        CPA_WAIT(STAGES - 2);
        __syncthreads();
        if (kt + STAGES - 1 < KT) ld_stage(kt + STAGES - 1);
        CPA_COMMIT();

        const int st = kt & (STAGES - 1);
        const uint32_t* a_s = (const uint32_t*)(AsBase + st * ASZ);
        const uint32_t* b_s = (const uint32_t*)(BsBase + st * BSZ);
#pragma unroll
        for (int g = 0; g < 2; g++) {     // two k16 groups per stage
            unsigned af[2][4], bf[8][2];
#pragma unroll
            for (int mt = 0; mt < 2; mt++) {
                int mb = wm + mt * 16 + r;
                if (AKM) {
                    af[mt][0] = a_s[(g * 8 + cq) * PADB + mb];
                    af[mt][1] = a_s[(g * 8 + cq) * PADB + mb + 8];
                    af[mt][2] = a_s[(g * 8 + 4 + cq) * PADB + mb];
                    af[mt][3] = a_s[(g * 8 + 4 + cq) * PADB + mb + 8];
                } else {
                    int bi = mb * 20 + g * 8 + cq;   // uint units (ROWH/2=20)
                    af[mt][0] = a_s[bi];
                    af[mt][1] = a_s[bi + 160];       // m+8 rows
                    af[mt][2] = a_s[bi + 4];         // k+8 halves
                    af[mt][3] = a_s[bi + 164];
                }
            }
#pragma unroll
            for (int nt = 0; nt < 8; nt++) {
                int nb = wn + nt * 8 + r;
                bf[nt][0] = b_s[(g * 8 + cq) * PADB + nb];
                bf[nt][1] = b_s[(g * 8 + 4 + cq) * PADB + nb];
            }
#pragma unroll
            for (int mt = 0; mt < 2; mt++)
#pragma unroll
                for (int nt = 0; nt < 8; nt++)
                    mma_f16(acc[mt][nt], af[mt], bf[nt]);
        }
    }

    // ---- epilogue ----
#pragma unroll
    for (int mt = 0; mt < 2; mt++) {
#pragma unroll
        for (int nt = 0; nt < 8; nt++) {
            int row = m0 + wm + mt * 16 + r;
            int col = n0 + wn + nt * 8 + 2 * cq;
            if (col < N) {
                float b0 = bias[col], b1 = bias[col + 1];
#pragma unroll
                for (int hh = 0; hh < 2; hh++) {
                    int rr = row + hh * 8;
                    float v0 = acc[mt][nt][hh * 2 + 0] + b0;
                    float v1 = acc[mt][nt][hh * 2 + 1] + b1;
                    if (resid) {
                        float2 rv = *(const float2*)(resid + (size_t)rr * N + col);
                        v0 += rv.x; v1 += rv.y;
                    }
                    if (RELU) { v0 = fmaxf(v0, 0.f); v1 = fmaxf(v1, 0.f); }
                    if (HOUT) {
                        *(__half2*)(Ch + (size_t)rr * N + col) = __floats2half2_rn(v0, v1);
                    } else {
                        *(float2*)(Cf + (size_t)rr * N + col) = make_float2(v0, v1);
                        if (AUXQP) {
                            int ww = rr & 127, hr = rr >> 7;
                            float p0, p1;
                            if (col < 128) {
                                p0 = Pcol[ww * 128 + col];
                                p1 = Pcol[ww * 128 + col + 1];
                            } else {
                                p0 = Prow[hr * 128 + col - 128];
                                p1 = Prow[hr * 128 + col - 127];
                            }
                            *(__half2*)(Caux + (size_t)rr * 256 + col) =
                                __floats2half2_rn(v0 + p0, v1 + p1);
                        }
                    }
                }
            }
        }
    }
}

// ---------------- fused softmax + bilinear deformable sampling ----------------
// grid NQ/4, block (32,16): warp=(query,head).
// Quarter-warp point-split: quarter lane>>3 handles 5 points; each lane loads
// uint4 = 8 halves (8 lanes cover the 64-half head row). 20 LDG.128/warp.
__global__ void __launch_bounds__(512) sample_kernel(
        const float* __restrict__ offaw,
        const __half* __restrict__ val,
        __half* __restrict__ acc) {
    int w = threadIdx.y;
    int n = blockIdx.x * 4 + (w >> 2);
    int h = w & 3;
    int lane = threadIdx.x;

    float logit = (lane < 20) ? offaw[(size_t)n * NOA + 160 + h * 20 + lane] : -INFINITY;
    float mx = logit;
#pragma unroll
    for (int s = 16; s; s >>= 1) mx = fmaxf(mx, __shfl_xor_sync(0xFFFFFFFFu, mx, s));
    float e = (lane < 20) ? __expf(logit - mx) : 0.f;
    float sum = e;
#pragma unroll
    for (int s = 16; s; s >>= 1) sum += __shfl_xor_sync(0xFFFFFFFFu, sum, s);
    float w_sm = e / sum;

    float px = 0.f, py = 0.f;
    if (lane < 20) {
        int l = lane >> 2, p = lane & 3;
        int j = ((h * LL + l) * PP + p) * 2;
        float ox = offaw[(size_t)n * NOA + j];
        float oy = offaw[(size_t)n * NOA + j + 1];
        px = (float)(n & 127) + ox;
        py = (float)(n >> 7) + oy;
    }

    const int qid = lane >> 3;        // quarter id 0..3
    const int i8 = (lane & 7) * 8;    // 8-half column offset within head
    float a[8] = {0.f, 0.f, 0.f, 0.f, 0.f, 0.f, 0.f, 0.f};
    for (int pp = 0; pp < 5; pp++) {
        int p = qid * 5 + pp;
        float x  = __shfl_sync(0xFFFFFFFFu, px, p);
        float y  = __shfl_sync(0xFFFFFFFFu, py, p);
        float wp = __shfl_sync(0xFFFFFFFFu, w_sm, p);
        int l = p >> 2;
        float x0f = floorf(x), y0f = floorf(y);
        float fx = x - x0f, fy = y - y0f;
        int x0 = (int)x0f, y0 = (int)y0f;
        const __half* base = val + (size_t)l * NQ * EE + h * HDD + i8;
#pragma unroll
        for (int dy = 0; dy < 2; dy++) {
#pragma unroll
            for (int dx = 0; dx < 2; dx++) {
                int ix = x0 + dx, iy = y0 + dy;
                bool valid = (ix >= 0) & (ix < 128) & (iy >= 0) & (iy < 128);
                float cw = ((dx ? fx : 1.f - fx) * (dy ? fy : 1.f - fy)) * wp;
                cw = valid ? cw : 0.f;
                int cx = min(max(ix, 0), 127);
                int cy = min(max(iy, 0), 127);
                int sidx = cy * 128 + cx;
                uint4 gv = *(const uint4*)(base + (size_t)sidx * EE);
                float2 f0 = __half22float2(*(__half2*)&gv.x);
                float2 f1 = __half22float2(*(__half2*)&gv.y);
                float2 f2 = __half22float2(*(__half2*)&gv.z);
                float2 f3 = __half22float2(*(__half2*)&gv.w);
                a[0] += cw * f0.x; a[1] += cw * f0.y;
                a[2] += cw * f1.x; a[3] += cw * f1.y;
                a[4] += cw * f2.x; a[5] += cw * f2.y;
                a[6] += cw * f3.x; a[7] += cw * f3.y;
            }
        }
    }
    // combine quarters
#pragma unroll
    for (int k = 0; k < 8; k++) {
        a[k] += __shfl_xor_sync(0xFFFFFFFFu, a[k], 8);
        a[k] += __shfl_xor_sync(0xFFFFFFFFu, a[k], 16);
    }
    if (qid == 0) {
        int c0 = h * HDD + i8;
        __half2 h0 = __floats2half2_rn(a[0], a[1]);
        __half2 h1 = __floats2half2_rn(a[2], a[3]);
        __half2 h2 = __floats2half2_rn(a[4], a[5]);
        __half2 h3 = __floats2half2_rn(a[6], a[7]);
        *(uint4*)(acc + (size_t)n * EE + c0) =
            make_uint4(*(unsigned*)&h0, *(unsigned*)&h1, *(unsigned*)&h2, *(unsigned*)&h3);
    }
}

// ---------------- row LayerNorm over E=256 + half copies ----------------
__global__ void ln_kernel(float* __restrict__ x, const float* __restrict__ g,
                          const float* __restrict__ b,
                          __half* __restrict__ rOut,
                          const float* __restrict__ prow, const float* __restrict__ pcol,
                          __half* __restrict__ qpOut) {
    int row = blockIdx.x * 8 + threadIdx.y;
    int lane = threadIdx.x;
    float* xr = x + (size_t)row * 256 + lane * 8;
    float4 v0 = *(const float4*)xr;
    float4 v1 = *(const float4*)(xr + 4);
    float o[8] = {v0.x, v0.y, v0.z, v0.w, v1.x, v1.y, v1.z, v1.w};
    float s = 0.f, q2 = 0.f;
#pragma unroll
    for (int k = 0; k < 8; k++) { s += o[k]; q2 += o[k] * o[k]; }
#pragma unroll
    for (int sh = 16; sh; sh >>= 1) {
        s  += __shfl_xor_sync(0xFFFFFFFFu, s, sh);
        q2 += __shfl_xor_sync(0xFFFFFFFFu, q2, sh);
    }
    float mean = s * (1.f / 256.f);
    float var = q2 * (1.f / 256.f) - mean * mean;
    float rstd = rsqrtf(var + 1e-5f);
    int ecol = lane * 8;
#pragma unroll
    for (int k = 0; k < 8; k++) o[k] = (o[k] - mean) * rstd * g[ecol + k] + b[ecol + k];
    *(float4*)xr       = make_float4(o[0], o[1], o[2], o[3]);
    *(float4*)(xr + 4) = make_float4(o[4], o[5], o[6], o[7]);
    size_t base = (size_t)row * 256 + ecol;
    if (rOut) {
        __half2 p0 = __floats2half2_rn(o[0], o[1]);
        __half2 p1 = __floats2half2_rn(o[2], o[3]);
        __half2 p2 = __floats2half2_rn(o[4], o[5]);
        __half2 p3 = __floats2half2_rn(o[6], o[7]);
        *(uint4*)(rOut + base) = make_uint4(*(unsigned*)&p0, *(unsigned*)&p1,
                                            *(unsigned*)&p2, *(unsigned*)&p3);
    }
    if (qpOut) {
        int ww = row & 127, hr = row >> 7;
        const float* psrc = (ecol < 128) ? (pcol + ww * 128 + ecol)
                                         : (prow + hr * 128 + (ecol - 128));
        float p[8];
        *(float4*)p       = *(const float4*)psrc;
        *(float4*)(p + 4) = *(const float4*)(psrc + 4);
        __half2 q0 = __floats2half2_rn(o[0] + p[0], o[1] + p[1]);
        __half2 q1 = __floats2half2_rn(o[2] + p[2], o[3] + p[3]);
        __half2 q2h = __floats2half2_rn(o[4] + p[4], o[5] + p[5]);
        __half2 q3 = __floats2half2_rn(o[6] + p[6], o[7] + p[7]);
        *(uint4*)(qpOut + base) = make_uint4(*(unsigned*)&q0, *(unsigned*)&q1,
                                             *(unsigned*)&q2h, *(unsigned*)&q3);
    }
}

// ---------------- final transpose ----------------
__global__ void transpose_kernel(float* __restrict__ out) {
    __shared__ float t[32][33];
    int n0 = blockIdx.x * 32, e0 = blockIdx.y * 32;
    int tx = threadIdx.x, ty = threadIdx.y;
#pragma unroll
    for (int i = 0; i < 32; i += 8)
        t[ty + i][tx] = g_q[(size_t)(n0 + ty + i) * 256 + e0 + tx];
    __syncthreads();
#pragma unroll
    for (int i = 0; i < 32; i += 8)
        out[(size_t)(e0 + ty + i) * NQ + n0 + tx] = t[tx][ty + i];
}

// ---------------- host orchestration ----------------
extern "C" void kernel_launch(void* const* d_in, const int* in_sizes, int n_in,
                              void* d_out, int out_size) {
    const float* feat   = (const float*)d_in[0];
    const float* n0g    = (const float*)d_in[1];
    const float* n0b    = (const float*)d_in[2];
    const float* in_w   = (const float*)d_in[3];
    const float* in_b   = (const float*)d_in[4];
    const float* prow   = (const float*)d_in[5];
    const float* pcol   = (const float*)d_in[6];
    const float* off_w  = (const float*)d_in[7];
    const float* off_b  = (const float*)d_in[8];
    const float* aw_w   = (const float*)d_in[9];
    const float* aw_b   = (const float*)d_in[10];
    const float* val_w  = (const float*)d_in[11];
    const float* val_b  = (const float*)d_in[12];
    const float* out_w  = (const float*)d_in[13];
    const float* out_b  = (const float*)d_in[14];
    const float* ln1_g  = (const float*)d_in[15];
    const float* ln1_b  = (const float*)d_in[16];
    const float* ln2_g  = (const float*)d_in[17];
    const float* ln2_b  = (const float*)d_in[18];
    const float* ffn_w1 = (const float*)d_in[19];
    const float* ffn_b1 = (const float*)d_in[20];
    const float* ffn_w2 = (const float*)d_in[21];
    const float* ffn_b2 = (const float*)d_in[22];

    __half *pf, *pqr, *pqp, *pval, *pacc, *ph;
    float *pq, *poa, *pboa;
    __half2 *pwin, *pwoa, *pwval, *pwout, *pwf1, *pwf2;
    cudaGetSymbolAddress((void**)&pf,    g_f);
    cudaGetSymbolAddress((void**)&pq,    g_q);
    cudaGetSymbolAddress((void**)&pqr,   g_qr);
    cudaGetSymbolAddress((void**)&pqp,   g_qp);
    cudaGetSymbolAddress((void**)&poa,   g_offaw);
    cudaGetSymbolAddress((void**)&pval,  g_val);
    cudaGetSymbolAddress((void**)&pacc,  g_acc);
    cudaGetSymbolAddress((void**)&ph,    g_h);
    cudaGetSymbolAddress((void**)&pwin,  g_w_in);
    cudaGetSymbolAddress((void**)&pwoa,  g_w_oa);
    cudaGetSymbolAddress((void**)&pwval, g_w_val);
    cudaGetSymbolAddress((void**)&pwout, g_w_out);
    cudaGetSymbolAddress((void**)&pwf1,  g_w_f1);
    cudaGetSymbolAddress((void**)&pwf2,  g_w_f2);
    cudaGetSymbolAddress((void**)&pboa,  g_b_oa);

    cudaFuncSetAttribute(gemm_h<true, false, false, true>,
                         cudaFuncAttributeMaxDynamicSharedMemorySize, AKM_SMEM);
    cudaFuncSetAttribute(gemm_h<true, false, true, false>,
                         cudaFuncAttributeMaxDynamicSharedMemorySize, AKM_SMEM);
    cudaFuncSetAttribute(gemm_h<false, false, false, false>,
                         cudaFuncAttributeMaxDynamicSharedMemorySize, ROW_SMEM);
    cudaFuncSetAttribute(gemm_h<false, true, true, false>,
                         cudaFuncAttributeMaxDynamicSharedMemorySize, ROW_SMEM);

    // ---- prologue: pack weights to half2, norm0 ----
    wpack_kernel<<<dim3((640 * 256 + 255) / 256, 1, 1), 256>>>(in_w, pwin, 1280, 256, 0, 0);
    wpack_kernel<<<dim3((128 * 256 + 255) / 256, 1, NLAY), 256>>>(
        val_w, pwval, 256, 256, (size_t)256 * 256, (size_t)128 * 256);
    wpack_kernel<<<dim3((128 * 256 + 255) / 256, 1, NLAY), 256>>>(
        out_w, pwout, 256, 256, (size_t)256 * 256, (size_t)128 * 256);
    wpack_kernel<<<dim3((128 * 512 + 255) / 256, 1, NLAY), 256>>>(
        ffn_w1, pwf1, 256, 512, (size_t)256 * 512, (size_t)128 * 512);
    wpack_kernel<<<dim3((256 * 256 + 255) / 256, 1, NLAY), 256>>>(
        ffn_w2, pwf2, 512, 256, (size_t)512 * 256, (size_t)256 * 256);
    pack_oa_kernel<<<(NLAY * 128 * NOA + 255) / 256, 256>>>(off_w, off_b, aw_w, aw_b);
    norm0_kernel<<<dim3(NQ / 256, LL), 256>>>(feat, n0g, n0b);

    // input_proj (AKM, K=1280, level hop every 128 half2 rows); aux qp half
    gemm_h<true, false, false, true><<<dim3(2, 128), 256, AKM_SMEM>>>(
        nullptr, (const __half2*)pf, pwin, in_b, nullptr, pq, nullptr, pqp, prow, pcol,
        256, 1280, 0, NQ, 7, (size_t)128 * NQ, 0, 0);

    for (int i = 0; i < NLAY; i++) {
        // offsets + aw logits (N=240), A = qp half row-major
        gemm_h<false, false, false, false><<<dim3(2, 128), 256, ROW_SMEM>>>(
            pqp, nullptr, pwoa + (size_t)i * 128 * NOA, pboa + (size_t)i * NOA, nullptr,
            poa, nullptr, nullptr, nullptr, nullptr,
            NOA, 256, 256, 0, 30, 0, 0, 0);
        // val projection, 5 levels via grid.z (AKM), half output
        gemm_h<true, false, true, false><<<dim3(2, 128, LL), 256, AKM_SMEM>>>(
            nullptr, (const __half2*)pf, pwval + (size_t)i * 128 * 256,
            val_b + (size_t)i * EE, nullptr, nullptr, pval, nullptr, nullptr, nullptr,
            256, 256, 0, NQ, 30, 0, (size_t)128 * NQ, (size_t)NQ * EE);
        // sampling (quarter-warp split, half val) -> half acc
        sample_kernel<<<NQ / 4, dim3(32, 16)>>>(poa, pval, pacc);
        // out proj + residual into q (fp32)
        gemm_h<false, false, false, false><<<dim3(2, 128), 256, ROW_SMEM>>>(
            pacc, nullptr, pwout + (size_t)i * 128 * 256, out_b + (size_t)i * EE, pq,
            pq, nullptr, nullptr, nullptr, nullptr,
            256, 256, 256, 0, 30, 0, 0, 0);
        ln_kernel<<<NQ / 8, dim3(32, 8)>>>(pq, ln1_g + (size_t)i * EE, ln1_b + (size_t)i * EE,
                                           pqr, nullptr, nullptr, nullptr);
        // ffn1: relu, half output h
        gemm_h<false, true, true, false><<<dim3(4, 128), 256, ROW_SMEM>>>(
            pqr, nullptr, pwf1 + (size_t)i * 128 * 512, ffn_b1 + (size_t)i * FFH, nullptr,
            nullptr, ph, nullptr, nullptr, nullptr,
            512, 256, 256, 0, 30, 0, 0, 0);
        // ffn2 + residual into q
        gemm_h<false, false, false, false><<<dim3(2, 128), 256, ROW_SMEM>>>(
            ph, nullptr, pwf2 + (size_t)i * 256 * 256, ffn_b2 + (size_t)i * EE, pq,
            pq, nullptr, nullptr, nullptr, nullptr,
            256, 512, 512, 0, 30, 0, 0, 0);
        // ln2: q fp32 + qp = half(q + pos)
        ln_kernel<<<NQ / 8, dim3(32, 8)>>>(pq, ln2_g + (size_t)i * EE, ln2_b + (size_t)i * EE,
                                           nullptr, prow, pcol, pqp);
    }

    transpose_kernel<<<dim3(NQ / 32, EE / 32), dim3(32, 8)>>>((float*)d_out);
}